// round 4
// baseline (speedup 1.0000x reference)
#include <cuda_runtime.h>
#include <math.h>

// Problem constants
#define T_TOT 8192   // B*N tokens
#define DD    1024
#define EE    8
#define RR    256

typedef unsigned long long u64;

// -------- scratch (__device__ globals; no allocations allowed) --------
__device__ int   g_count[EE];
__device__ int   g_sidx[EE * T_TOT];     // sidx = token*2 + k
__device__ float g_gate[EE * T_TOT];
__device__ float g_S[T_TOT * 2 * RR];    // 16 MB: gated silu(u)*v rows

// -------- f32x2 helpers (packed fp32 pipe, 2 FMA / instr) --------
__device__ __forceinline__ u64 fma2(u64 a, u64 b, u64 c) {
    u64 d;
    asm("fma.rn.f32x2 %0, %1, %2, %3;" : "=l"(d) : "l"(a), "l"(b), "l"(c));
    return d;
}
__device__ __forceinline__ u64 splat2(float v) {
    u64 d; unsigned r = __float_as_uint(v);
    asm("mov.b64 %0, {%1, %1};" : "=l"(d) : "r"(r));
    return d;
}
__device__ __forceinline__ float2 unpack2(u64 a) {
    unsigned lo, hi;
    asm("mov.b64 {%0, %1}, %2;" : "=r"(lo), "=r"(hi) : "l"(a));
    return make_float2(__uint_as_float(lo), __uint_as_float(hi));
}

// -------- init: zero output + counters --------
__global__ void init_kernel(float4* out4, int n4) {
    if (blockIdx.x == 0 && threadIdx.x < EE) g_count[threadIdx.x] = 0;
    int stride = gridDim.x * blockDim.x;
    for (int i = blockIdx.x * blockDim.x + threadIdx.x; i < n4; i += stride)
        out4[i] = make_float4(0.f, 0.f, 0.f, 0.f);
}

// -------- router: one warp per token --------
__global__ void router_kernel(const float* __restrict__ x,
                              const float* __restrict__ gw) {
    int warp = (blockIdx.x * blockDim.x + threadIdx.x) >> 5;
    int lane = threadIdx.x & 31;
    if (warp >= T_TOT) return;
    const float* xr = x + (size_t)warp * DD;

    float acc[EE];
#pragma unroll
    for (int e = 0; e < EE; e++) acc[e] = 0.f;

    for (int d = lane * 4; d < DD; d += 32 * 4) {
        float4 xv = *(const float4*)(xr + d);
        const float* xp = (const float*)&xv;
#pragma unroll
        for (int j = 0; j < 4; j++) {
            float xs = xp[j];
            float4 g0 = *(const float4*)(gw + (size_t)(d + j) * EE);
            float4 g1 = *(const float4*)(gw + (size_t)(d + j) * EE + 4);
            acc[0] += xs * g0.x; acc[1] += xs * g0.y;
            acc[2] += xs * g0.z; acc[3] += xs * g0.w;
            acc[4] += xs * g1.x; acc[5] += xs * g1.y;
            acc[6] += xs * g1.z; acc[7] += xs * g1.w;
        }
    }
#pragma unroll
    for (int e = 0; e < EE; e++)
#pragma unroll
        for (int off = 16; off; off >>= 1)
            acc[e] += __shfl_xor_sync(0xFFFFFFFFu, acc[e], off);

    if (lane == 0) {
        int i0 = 0; float v0 = acc[0];
#pragma unroll
        for (int e = 1; e < EE; e++) if (acc[e] > v0) { v0 = acc[e]; i0 = e; }
        int i1 = -1; float v1 = -INFINITY;
#pragma unroll
        for (int e = 0; e < EE; e++) if (e != i0 && acc[e] > v1) { v1 = acc[e]; i1 = e; }
        float w0 = 1.f / (1.f + expf(v1 - v0));   // softmax over (v0,v1), v0 = max
        float w1 = 1.f - w0;
        int p0 = atomicAdd(&g_count[i0], 1);
        g_sidx[i0 * T_TOT + p0] = warp * 2 + 0;
        g_gate[i0 * T_TOT + p0] = w0;
        int p1 = atomicAdd(&g_count[i1], 1);
        g_sidx[i1 * T_TOT + p1] = warp * 2 + 1;
        g_gate[i1 * T_TOT + p1] = w1;
    }
}

// -------- pass1: S = gate * silu(x Wu_e) * (x Wv_e), tiles of 32 rows x 256 (=R) --------
#define TM1 32
#define TK1 16
__global__ __launch_bounds__(256, 2)
void pass1_kernel(const float* __restrict__ x,
                  const float* __restrict__ Wu,
                  const float* __restrict__ Wv) {
    int e = blockIdx.y;
    int cnt = g_count[e];
    int mbase = blockIdx.x * TM1;
    if (mbase >= cnt) return;

    __shared__ __align__(16) float xs[TK1][TM1];     // [k][m]
    __shared__ __align__(16) float wus[TK1][RR];
    __shared__ __align__(16) float wvs[TK1][RR];
    __shared__ int   s_tok[TM1];
    __shared__ int   s_sidx[TM1];
    __shared__ float s_gate[TM1];

    int tid = threadIdx.x;
    if (tid < TM1) {
        int slot = mbase + tid;
        bool valid = slot < cnt;
        int sidx = valid ? g_sidx[e * T_TOT + slot] : -1;
        s_sidx[tid] = sidx;
        s_tok[tid]  = valid ? (sidx >> 1) : 0;
        s_gate[tid] = valid ? g_gate[e * T_TOT + slot] : 0.f;
    }
    __syncthreads();

    int nx  = tid & 63;       // 64 groups over R: n0 = nx*4
    int my  = tid >> 6;       // 4 groups over M: m0l = my*8
    int n0  = nx * 4;
    int m0l = my * 8;

    u64 accU[4][4], accV[4][4];
#pragma unroll
    for (int i = 0; i < 4; i++)
#pragma unroll
        for (int j = 0; j < 4; j++) { accU[i][j] = 0ull; accV[i][j] = 0ull; }

    const float* WuE = Wu + (size_t)e * DD * RR;
    const float* WvE = Wv + (size_t)e * DD * RR;

    for (int d0 = 0; d0 < DD; d0 += TK1) {
        // gather x tile (transposed) : 32 rows x 16 k
        if (tid < 128) {
            int m = tid >> 2, kb = (tid & 3) * 4;
            float4 xv = *(const float4*)(x + (size_t)s_tok[m] * DD + d0 + kb);
            xs[kb + 0][m] = xv.x; xs[kb + 1][m] = xv.y;
            xs[kb + 2][m] = xv.z; xs[kb + 3][m] = xv.w;
        }
        // gather weight tiles : 16 x 256 each
#pragma unroll
        for (int i = 0; i < 4; i++) {
            int slot = tid + i * 256;
            int k = slot >> 6, c = (slot & 63) << 2;
            *(float4*)&wus[k][c] = *(const float4*)(WuE + (size_t)(d0 + k) * RR + c);
            *(float4*)&wvs[k][c] = *(const float4*)(WvE + (size_t)(d0 + k) * RR + c);
        }
        __syncthreads();
#pragma unroll
        for (int kk = 0; kk < TK1; kk++) {
            ulonglong2 xa = *(const ulonglong2*)&xs[kk][m0l];
            ulonglong2 xb = *(const ulonglong2*)&xs[kk][m0l + 4];
            u64 xm[4] = { xa.x, xa.y, xb.x, xb.y };
            float4 wu4 = *(const float4*)&wus[kk][n0];
            float4 wv4 = *(const float4*)&wvs[kk][n0];
            u64 wu[4] = { splat2(wu4.x), splat2(wu4.y), splat2(wu4.z), splat2(wu4.w) };
            u64 wv[4] = { splat2(wv4.x), splat2(wv4.y), splat2(wv4.z), splat2(wv4.w) };
#pragma unroll
            for (int m2 = 0; m2 < 4; m2++)
#pragma unroll
                for (int n = 0; n < 4; n++) {
                    accU[m2][n] = fma2(xm[m2], wu[n], accU[m2][n]);
                    accV[m2][n] = fma2(xm[m2], wv[n], accV[m2][n]);
                }
        }
        __syncthreads();
    }

    // epilogue: s = gate * silu(u) * v  -> g_S[sidx]
#pragma unroll
    for (int m2 = 0; m2 < 4; m2++) {
#pragma unroll
        for (int h = 0; h < 2; h++) {
            int mrow = m0l + 2 * m2 + h;
            int slot = mbase + mrow;
            if (slot >= cnt) continue;
            int sidx = s_sidx[mrow];
            float g = s_gate[mrow];
            float4 sv;
            float* svp = (float*)&sv;
#pragma unroll
            for (int n = 0; n < 4; n++) {
                float2 u2 = unpack2(accU[m2][n]);
                float2 v2 = unpack2(accV[m2][n]);
                float u = h ? u2.y : u2.x;
                float v = h ? v2.y : v2.x;
                float sig = 1.f / (1.f + __expf(-u));
                svp[n] = g * (u * sig) * v;
            }
            *(float4*)(g_S + (size_t)sidx * RR + n0) = sv;
        }
    }
}

// -------- pass2: out[token] += S_row * Wo_e, tiles 64 rows x 128 cols, K=256 --------
#define TM2 64
#define TN2 128
#define TK2 32
__global__ __launch_bounds__(256, 2)
void pass2_kernel(const float* __restrict__ Wo, float* __restrict__ out) {
    int e = blockIdx.z;
    int cnt = g_count[e];
    int mbase = blockIdx.x * TM2;
    if (mbase >= cnt) return;
    int n0g = blockIdx.y * TN2;

    __shared__ __align__(16) float ss[TK2][TM2];    // 8 KB  [k][m]
    __shared__ __align__(16) float wos[TK2][TN2];   // 16 KB [k][n]
    __shared__ int s_tok[TM2];
    __shared__ int s_sidx[TM2];

    int tid = threadIdx.x;
    if (tid < TM2) {
        int slot = mbase + tid;
        bool valid = slot < cnt;
        int sidx = valid ? g_sidx[e * T_TOT + slot] : 0;  // 0 is a safe, valid row
        s_sidx[tid] = sidx;
        s_tok[tid]  = sidx >> 1;
    }
    __syncthreads();

    int nx  = tid & 31;       // n0 = nx*4 over 128
    int my  = tid >> 5;       // m0l = my*8 over 64
    int n0  = nx * 4;
    int m0l = my * 8;

    u64 acc[4][4];
#pragma unroll
    for (int i = 0; i < 4; i++)
#pragma unroll
        for (int j = 0; j < 4; j++) acc[i][j] = 0ull;

    const float* WoE = Wo + (size_t)e * RR * DD;

    for (int k0 = 0; k0 < RR; k0 += TK2) {
        // gather S tile (transposed): 64 rows x 32 k
#pragma unroll
        for (int i = 0; i < 2; i++) {
            int slot = tid + i * 256;
            int m = slot >> 3, kb = (slot & 7) << 2;
            float4 sv = *(const float4*)(g_S + (size_t)s_sidx[m] * RR + k0 + kb);
            ss[kb + 0][m] = sv.x; ss[kb + 1][m] = sv.y;
            ss[kb + 2][m] = sv.z; ss[kb + 3][m] = sv.w;
        }
        // gather Wo tile: 32 x 128
#pragma unroll
        for (int i = 0; i < 4; i++) {
            int slot = tid + i * 256;
            int k = slot >> 5, c = (slot & 31) << 2;
            *(float4*)&wos[k][c] =
                *(const float4*)(WoE + (size_t)(k0 + k) * DD + n0g + c);
        }
        __syncthreads();
#pragma unroll
        for (int kk = 0; kk < TK2; kk++) {
            ulonglong2 xa = *(const ulonglong2*)&ss[kk][m0l];
            ulonglong2 xb = *(const ulonglong2*)&ss[kk][m0l + 4];
            u64 xm[4] = { xa.x, xa.y, xb.x, xb.y };
            float4 w4 = *(const float4*)&wos[kk][n0];
            u64 w[4] = { splat2(w4.x), splat2(w4.y), splat2(w4.z), splat2(w4.w) };
#pragma unroll
            for (int m2 = 0; m2 < 4; m2++)
#pragma unroll
                for (int n = 0; n < 4; n++)
                    acc[m2][n] = fma2(xm[m2], w[n], acc[m2][n]);
        }
        __syncthreads();
    }

    // epilogue: atomic accumulate into out (each token has exactly 2 experts)
#pragma unroll
    for (int m2 = 0; m2 < 4; m2++) {
#pragma unroll
        for (int h = 0; h < 2; h++) {
            int mrow = m0l + 2 * m2 + h;
            int slot = mbase + mrow;
            if (slot >= cnt) continue;
            int t = s_tok[mrow];
            float* orow = out + (size_t)t * DD + n0g + n0;
#pragma unroll
            for (int n = 0; n < 4; n++) {
                float2 a2 = unpack2(acc[m2][n]);
                atomicAdd(orow + n, h ? a2.y : a2.x);
            }
        }
    }
}

// -------- launch --------
extern "C" void kernel_launch(void* const* d_in, const int* in_sizes, int n_in,
                              void* d_out, int out_size) {
    (void)in_sizes; (void)n_in;
    const float* x  = (const float*)d_in[0];
    const float* gw = (const float*)d_in[1];
    const float* Wu = (const float*)d_in[2];
    const float* Wv = (const float*)d_in[3];
    const float* Wo = (const float*)d_in[4];
    float* out = (float*)d_out;

    int n4 = out_size / 4;
    init_kernel<<<1024, 256>>>((float4*)out, n4);
    router_kernel<<<T_TOT / 8, 256>>>(x, gw);

    dim3 g1(T_TOT / TM1, EE);                 // 256 x 8 tiles (early-exit on count)
    pass1_kernel<<<g1, 256>>>(x, Wu, Wv);

    dim3 g2(T_TOT / TM2, DD / TN2, EE);       // 128 x 8 x 8 tiles
    pass2_kernel<<<g2, 256>>>(Wo, out);
}

// round 5
// speedup vs baseline: 1.0028x; 1.0028x over previous
#include <cuda_runtime.h>
#include <math.h>

// Problem constants
#define T_TOT 8192   // B*N tokens
#define DD    1024
#define EE    8
#define RR    256

typedef unsigned long long u64;

// -------- scratch (__device__ globals; no allocations allowed) --------
__device__ int   g_count[EE];
__device__ int   g_sidx[EE * T_TOT];     // sidx = token*2 + k
__device__ float g_gate[EE * T_TOT];
__device__ float g_S[T_TOT * 2 * RR];    // 16 MB: gated silu(u)*v rows

// -------- f32x2 helpers (packed fp32 pipe, 2 FMA / instr) --------
__device__ __forceinline__ u64 fma2(u64 a, u64 b, u64 c) {
    u64 d;
    asm("fma.rn.f32x2 %0, %1, %2, %3;" : "=l"(d) : "l"(a), "l"(b), "l"(c));
    return d;
}
__device__ __forceinline__ u64 splat2(float v) {
    u64 d; unsigned r = __float_as_uint(v);
    asm("mov.b64 %0, {%1, %1};" : "=l"(d) : "r"(r));
    return d;
}
__device__ __forceinline__ float2 unpack2(u64 a) {
    unsigned lo, hi;
    asm("mov.b64 {%0, %1}, %2;" : "=r"(lo), "=r"(hi) : "l"(a));
    return make_float2(__uint_as_float(lo), __uint_as_float(hi));
}

// -------- init: zero output + counters --------
__global__ void init_kernel(float4* out4, int n4) {
    if (blockIdx.x == 0 && threadIdx.x < EE) g_count[threadIdx.x] = 0;
    int stride = gridDim.x * blockDim.x;
    for (int i = blockIdx.x * blockDim.x + threadIdx.x; i < n4; i += stride)
        out4[i] = make_float4(0.f, 0.f, 0.f, 0.f);
}

// -------- router: one warp per token --------
__global__ void router_kernel(const float* __restrict__ x,
                              const float* __restrict__ gw) {
    int warp = (blockIdx.x * blockDim.x + threadIdx.x) >> 5;
    int lane = threadIdx.x & 31;
    if (warp >= T_TOT) return;
    const float* xr = x + (size_t)warp * DD;

    float acc[EE];
#pragma unroll
    for (int e = 0; e < EE; e++) acc[e] = 0.f;

    for (int d = lane * 4; d < DD; d += 32 * 4) {
        float4 xv = *(const float4*)(xr + d);
        const float* xp = (const float*)&xv;
#pragma unroll
        for (int j = 0; j < 4; j++) {
            float xs = xp[j];
            float4 g0 = *(const float4*)(gw + (size_t)(d + j) * EE);
            float4 g1 = *(const float4*)(gw + (size_t)(d + j) * EE + 4);
            acc[0] += xs * g0.x; acc[1] += xs * g0.y;
            acc[2] += xs * g0.z; acc[3] += xs * g0.w;
            acc[4] += xs * g1.x; acc[5] += xs * g1.y;
            acc[6] += xs * g1.z; acc[7] += xs * g1.w;
        }
    }
#pragma unroll
    for (int e = 0; e < EE; e++)
#pragma unroll
        for (int off = 16; off; off >>= 1)
            acc[e] += __shfl_xor_sync(0xFFFFFFFFu, acc[e], off);

    if (lane == 0) {
        int i0 = 0; float v0 = acc[0];
#pragma unroll
        for (int e = 1; e < EE; e++) if (acc[e] > v0) { v0 = acc[e]; i0 = e; }
        int i1 = -1; float v1 = -INFINITY;
#pragma unroll
        for (int e = 0; e < EE; e++) if (e != i0 && acc[e] > v1) { v1 = acc[e]; i1 = e; }
        float w0 = 1.f / (1.f + expf(v1 - v0));   // softmax over (v0,v1), v0 = max
        float w1 = 1.f - w0;
        int p0 = atomicAdd(&g_count[i0], 1);
        g_sidx[i0 * T_TOT + p0] = warp * 2 + 0;
        g_gate[i0 * T_TOT + p0] = w0;
        int p1 = atomicAdd(&g_count[i1], 1);
        g_sidx[i1 * T_TOT + p1] = warp * 2 + 1;
        g_gate[i1 * T_TOT + p1] = w1;
    }
}

// -------- pass1: S = gate * silu(x Wu_e) * (x Wv_e), tiles of 32 rows x 256 (=R) --------
#define TM1 32
#define TK1 16
__global__ __launch_bounds__(256, 2)
void pass1_kernel(const float* __restrict__ x,
                  const float* __restrict__ Wu,
                  const float* __restrict__ Wv) {
    int e = blockIdx.y;
    int cnt = g_count[e];
    int mbase = blockIdx.x * TM1;
    if (mbase >= cnt) return;

    __shared__ __align__(16) float xs[TK1][TM1];     // [k][m]
    __shared__ __align__(16) float wus[TK1][RR];
    __shared__ __align__(16) float wvs[TK1][RR];
    __shared__ int   s_tok[TM1];
    __shared__ int   s_sidx[TM1];
    __shared__ float s_gate[TM1];

    int tid = threadIdx.x;
    if (tid < TM1) {
        int slot = mbase + tid;
        bool valid = slot < cnt;
        int sidx = valid ? g_sidx[e * T_TOT + slot] : -1;
        s_sidx[tid] = sidx;
        s_tok[tid]  = valid ? (sidx >> 1) : 0;
        s_gate[tid] = valid ? g_gate[e * T_TOT + slot] : 0.f;
    }
    __syncthreads();

    int nx  = tid & 63;       // 64 groups over R: n0 = nx*4
    int my  = tid >> 6;       // 4 groups over M: m0l = my*8
    int n0  = nx * 4;
    int m0l = my * 8;

    u64 accU[4][4], accV[4][4];
#pragma unroll
    for (int i = 0; i < 4; i++)
#pragma unroll
        for (int j = 0; j < 4; j++) { accU[i][j] = 0ull; accV[i][j] = 0ull; }

    const float* WuE = Wu + (size_t)e * DD * RR;
    const float* WvE = Wv + (size_t)e * DD * RR;

    for (int d0 = 0; d0 < DD; d0 += TK1) {
        // gather x tile (transposed) : 32 rows x 16 k
        if (tid < 128) {
            int m = tid >> 2, kb = (tid & 3) * 4;
            float4 xv = *(const float4*)(x + (size_t)s_tok[m] * DD + d0 + kb);
            xs[kb + 0][m] = xv.x; xs[kb + 1][m] = xv.y;
            xs[kb + 2][m] = xv.z; xs[kb + 3][m] = xv.w;
        }
        // gather weight tiles : 16 x 256 each
#pragma unroll
        for (int i = 0; i < 4; i++) {
            int slot = tid + i * 256;
            int k = slot >> 6, c = (slot & 63) << 2;
            *(float4*)&wus[k][c] = *(const float4*)(WuE + (size_t)(d0 + k) * RR + c);
            *(float4*)&wvs[k][c] = *(const float4*)(WvE + (size_t)(d0 + k) * RR + c);
        }
        __syncthreads();
#pragma unroll
        for (int kk = 0; kk < TK1; kk++) {
            ulonglong2 xa = *(const ulonglong2*)&xs[kk][m0l];
            ulonglong2 xb = *(const ulonglong2*)&xs[kk][m0l + 4];
            u64 xm[4] = { xa.x, xa.y, xb.x, xb.y };
            float4 wu4 = *(const float4*)&wus[kk][n0];
            float4 wv4 = *(const float4*)&wvs[kk][n0];
            u64 wu[4] = { splat2(wu4.x), splat2(wu4.y), splat2(wu4.z), splat2(wu4.w) };
            u64 wv[4] = { splat2(wv4.x), splat2(wv4.y), splat2(wv4.z), splat2(wv4.w) };
#pragma unroll
            for (int m2 = 0; m2 < 4; m2++)
#pragma unroll
                for (int n = 0; n < 4; n++) {
                    accU[m2][n] = fma2(xm[m2], wu[n], accU[m2][n]);
                    accV[m2][n] = fma2(xm[m2], wv[n], accV[m2][n]);
                }
        }
        __syncthreads();
    }

    // epilogue: s = gate * silu(u) * v  -> g_S[sidx]
#pragma unroll
    for (int m2 = 0; m2 < 4; m2++) {
#pragma unroll
        for (int h = 0; h < 2; h++) {
            int mrow = m0l + 2 * m2 + h;
            int slot = mbase + mrow;
            if (slot >= cnt) continue;
            int sidx = s_sidx[mrow];
            float g = s_gate[mrow];
            float4 sv;
            float* svp = (float*)&sv;
#pragma unroll
            for (int n = 0; n < 4; n++) {
                float2 u2 = unpack2(accU[m2][n]);
                float2 v2 = unpack2(accV[m2][n]);
                float u = h ? u2.y : u2.x;
                float v = h ? v2.y : v2.x;
                float sig = 1.f / (1.f + __expf(-u));
                svp[n] = g * (u * sig) * v;
            }
            *(float4*)(g_S + (size_t)sidx * RR + n0) = sv;
        }
    }
}

// -------- pass2: out[token] += S_row * Wo_e, tiles 64 rows x 128 cols, K=256 --------
#define TM2 64
#define TN2 128
#define TK2 32
__global__ __launch_bounds__(256, 2)
void pass2_kernel(const float* __restrict__ Wo, float* __restrict__ out) {
    int e = blockIdx.z;
    int cnt = g_count[e];
    int mbase = blockIdx.x * TM2;
    if (mbase >= cnt) return;
    int n0g = blockIdx.y * TN2;

    __shared__ __align__(16) float ss[TK2][TM2];    // 8 KB  [k][m]
    __shared__ __align__(16) float wos[TK2][TN2];   // 16 KB [k][n]
    __shared__ int s_tok[TM2];
    __shared__ int s_sidx[TM2];

    int tid = threadIdx.x;
    if (tid < TM2) {
        int slot = mbase + tid;
        bool valid = slot < cnt;
        int sidx = valid ? g_sidx[e * T_TOT + slot] : 0;  // 0 is a safe, valid row
        s_sidx[tid] = sidx;
        s_tok[tid]  = sidx >> 1;
    }
    __syncthreads();

    int nx  = tid & 31;       // n0 = nx*4 over 128
    int my  = tid >> 5;       // m0l = my*8 over 64
    int n0  = nx * 4;
    int m0l = my * 8;

    u64 acc[4][4];
#pragma unroll
    for (int i = 0; i < 4; i++)
#pragma unroll
        for (int j = 0; j < 4; j++) acc[i][j] = 0ull;

    const float* WoE = Wo + (size_t)e * RR * DD;

    for (int k0 = 0; k0 < RR; k0 += TK2) {
        // gather S tile (transposed): 64 rows x 32 k
#pragma unroll
        for (int i = 0; i < 2; i++) {
            int slot = tid + i * 256;
            int m = slot >> 3, kb = (slot & 7) << 2;
            float4 sv = *(const float4*)(g_S + (size_t)s_sidx[m] * RR + k0 + kb);
            ss[kb + 0][m] = sv.x; ss[kb + 1][m] = sv.y;
            ss[kb + 2][m] = sv.z; ss[kb + 3][m] = sv.w;
        }
        // gather Wo tile: 32 x 128
#pragma unroll
        for (int i = 0; i < 4; i++) {
            int slot = tid + i * 256;
            int k = slot >> 5, c = (slot & 31) << 2;
            *(float4*)&wos[k][c] =
                *(const float4*)(WoE + (size_t)(k0 + k) * DD + n0g + c);
        }
        __syncthreads();
#pragma unroll
        for (int kk = 0; kk < TK2; kk++) {
            ulonglong2 xa = *(const ulonglong2*)&ss[kk][m0l];
            ulonglong2 xb = *(const ulonglong2*)&ss[kk][m0l + 4];
            u64 xm[4] = { xa.x, xa.y, xb.x, xb.y };
            float4 w4 = *(const float4*)&wos[kk][n0];
            u64 w[4] = { splat2(w4.x), splat2(w4.y), splat2(w4.z), splat2(w4.w) };
#pragma unroll
            for (int m2 = 0; m2 < 4; m2++)
#pragma unroll
                for (int n = 0; n < 4; n++)
                    acc[m2][n] = fma2(xm[m2], w[n], acc[m2][n]);
        }
        __syncthreads();
    }

    // epilogue: atomic accumulate into out (each token has exactly 2 experts)
#pragma unroll
    for (int m2 = 0; m2 < 4; m2++) {
#pragma unroll
        for (int h = 0; h < 2; h++) {
            int mrow = m0l + 2 * m2 + h;
            int slot = mbase + mrow;
            if (slot >= cnt) continue;
            int t = s_tok[mrow];
            float* orow = out + (size_t)t * DD + n0g + n0;
#pragma unroll
            for (int n = 0; n < 4; n++) {
                float2 a2 = unpack2(acc[m2][n]);
                atomicAdd(orow + n, h ? a2.y : a2.x);
            }
        }
    }
}

// -------- launch --------
extern "C" void kernel_launch(void* const* d_in, const int* in_sizes, int n_in,
                              void* d_out, int out_size) {
    (void)in_sizes; (void)n_in;
    const float* x  = (const float*)d_in[0];
    const float* gw = (const float*)d_in[1];
    const float* Wu = (const float*)d_in[2];
    const float* Wv = (const float*)d_in[3];
    const float* Wo = (const float*)d_in[4];
    float* out = (float*)d_out;

    int n4 = out_size / 4;
    init_kernel<<<1024, 256>>>((float4*)out, n4);
    router_kernel<<<T_TOT / 8, 256>>>(x, gw);

    dim3 g1(T_TOT / TM1, EE);                 // 256 x 8 tiles (early-exit on count)
    pass1_kernel<<<g1, 256>>>(x, Wu, Wv);

    dim3 g2(T_TOT / TM2, DD / TN2, EE);       // 128 x 8 x 8 tiles
    pass2_kernel<<<g2, 256>>>(Wo, out);
}

// round 7
// speedup vs baseline: 1.4958x; 1.4916x over previous
#include <cuda_runtime.h>
#include <cuda_bf16.h>
#include <math.h>
#include <stdint.h>

// Problem constants
#define T_TOT 8192   // B*N tokens
#define DD    1024
#define EE    8
#define RR    256
#define NSLOT (T_TOT * 2)

// -------- scratch (__device__ globals; no allocations allowed) --------
__device__ int   g_count[EE];
__device__ int   g_sidx[EE * T_TOT];          // sidx = token*2 + k
__device__ float g_gate[EE * T_TOT];
__device__ __nv_bfloat16 g_xh[T_TOT * DD];    // x hi/lo split
__device__ __nv_bfloat16 g_xl[T_TOT * DD];
__device__ __nv_bfloat16 g_sh[NSLOT * RR];    // s = gate*silu(u)*v hi/lo
__device__ __nv_bfloat16 g_sl[NSLOT * RR];
// pass1 B packed: [e][nt(4)][n(128)][k'(3072)]; n<64: Wu row 64nt+n, else Wv row 64nt+n-64
// k' chunks: [0,1024)=hi, [1024,2048)=lo, [2048,3072)=hi   (A chunks: xh, xh, xl)
__device__ __nv_bfloat16 g_w1[EE * 4 * 128 * 3072];
// pass2 B packed: [e][d(1024)][k'(768)]; k' chunks: [0,256)=Wo hi, [256,512)=lo, [512,768)=hi
__device__ __nv_bfloat16 g_wop[EE * DD * 768];

// -------- PTX helpers (base sm_103 features only) --------
__device__ __forceinline__ uint32_t smem_u32(const void* p) {
    uint32_t a;
    asm("{ .reg .u64 t; cvta.to.shared.u64 t, %1; cvt.u32.u64 %0, t; }" : "=r"(a) : "l"(p));
    return a;
}
__device__ __forceinline__ void cp16(uint32_t dst, const void* src) {
    asm volatile("cp.async.cg.shared.global [%0], [%1], 16;" :: "r"(dst), "l"(src));
}
#define CP_COMMIT() asm volatile("cp.async.commit_group;" ::: "memory")
#define CP_WAIT1()  asm volatile("cp.async.wait_group 1;" ::: "memory")
#define CP_WAIT0()  asm volatile("cp.async.wait_group 0;" ::: "memory")

__device__ __forceinline__ void ldsm_x4(uint32_t r[4], uint32_t addr) {
    asm volatile("ldmatrix.sync.aligned.m8n8.x4.shared.b16 {%0,%1,%2,%3}, [%4];"
                 : "=r"(r[0]), "=r"(r[1]), "=r"(r[2]), "=r"(r[3]) : "r"(addr));
}
__device__ __forceinline__ void mma_bf16(float c[4],
                                         uint32_t a0, uint32_t a1, uint32_t a2, uint32_t a3,
                                         uint32_t b0, uint32_t b1) {
    asm("mma.sync.aligned.m16n8k16.row.col.f32.bf16.bf16.f32 "
        "{%0,%1,%2,%3}, {%4,%5,%6,%7}, {%8,%9}, {%0,%1,%2,%3};"
        : "+f"(c[0]), "+f"(c[1]), "+f"(c[2]), "+f"(c[3])
        : "r"(a0), "r"(a1), "r"(a2), "r"(a3), "r"(b0), "r"(b1));
}
// SW128 swizzle for 128B rows: byte offset for (row, 16B-group g)
__device__ __forceinline__ uint32_t sw_off(int row, int g) {
    return (uint32_t)row * 128u + (uint32_t)((g ^ (row & 7)) << 4);
}
__device__ __forceinline__ void split_bf16(float v, __nv_bfloat16& h, __nv_bfloat16& l) {
    h = __float2bfloat16_rn(v);
    l = __float2bfloat16_rn(v - __bfloat162float(h));
}

// -------- init: zero output + counters --------
__global__ void init_kernel(float4* out4, int n4) {
    if (blockIdx.x == 0 && threadIdx.x < EE) g_count[threadIdx.x] = 0;
    int stride = gridDim.x * blockDim.x;
    for (int i = blockIdx.x * blockDim.x + threadIdx.x; i < n4; i += stride)
        out4[i] = make_float4(0.f, 0.f, 0.f, 0.f);
}

// -------- router: one warp per token --------
__global__ void router_kernel(const float* __restrict__ x,
                              const float* __restrict__ gw) {
    int warp = (blockIdx.x * blockDim.x + threadIdx.x) >> 5;
    int lane = threadIdx.x & 31;
    if (warp >= T_TOT) return;
    const float* xr = x + (size_t)warp * DD;

    float acc[EE];
#pragma unroll
    for (int e = 0; e < EE; e++) acc[e] = 0.f;

    for (int d = lane * 4; d < DD; d += 32 * 4) {
        float4 xv = *(const float4*)(xr + d);
        const float* xp = (const float*)&xv;
#pragma unroll
        for (int j = 0; j < 4; j++) {
            float xs = xp[j];
            float4 g0 = *(const float4*)(gw + (size_t)(d + j) * EE);
            float4 g1 = *(const float4*)(gw + (size_t)(d + j) * EE + 4);
            acc[0] += xs * g0.x; acc[1] += xs * g0.y;
            acc[2] += xs * g0.z; acc[3] += xs * g0.w;
            acc[4] += xs * g1.x; acc[5] += xs * g1.y;
            acc[6] += xs * g1.z; acc[7] += xs * g1.w;
        }
    }
#pragma unroll
    for (int e = 0; e < EE; e++)
#pragma unroll
        for (int off = 16; off; off >>= 1)
            acc[e] += __shfl_xor_sync(0xFFFFFFFFu, acc[e], off);

    if (lane == 0) {
        int i0 = 0; float v0 = acc[0];
#pragma unroll
        for (int e = 1; e < EE; e++) if (acc[e] > v0) { v0 = acc[e]; i0 = e; }
        int i1 = -1; float v1 = -INFINITY;
#pragma unroll
        for (int e = 0; e < EE; e++) if (e != i0 && acc[e] > v1) { v1 = acc[e]; i1 = e; }
        float w0 = 1.f / (1.f + expf(v1 - v0));
        float w1 = 1.f - w0;
        int p0 = atomicAdd(&g_count[i0], 1);
        g_sidx[i0 * T_TOT + p0] = warp * 2 + 0;
        g_gate[i0 * T_TOT + p0] = w0;
        int p1 = atomicAdd(&g_count[i1], 1);
        g_sidx[i1 * T_TOT + p1] = warp * 2 + 1;
        g_gate[i1 * T_TOT + p1] = w1;
    }
}

// -------- prep: split x into bf16 hi/lo --------
__global__ void split_x_kernel(const float4* __restrict__ x4) {
    int n4 = T_TOT * DD / 4;
    int stride = gridDim.x * blockDim.x;
    for (int i = blockIdx.x * blockDim.x + threadIdx.x; i < n4; i += stride) {
        float4 v = x4[i];
        const float* vp = (const float*)&v;
        __nv_bfloat16 h[4], l[4];
#pragma unroll
        for (int j = 0; j < 4; j++) split_bf16(vp[j], h[j], l[j]);
        *(uint2*)(g_xh + (size_t)i * 4) = *(const uint2*)h;
        *(uint2*)(g_xl + (size_t)i * 4) = *(const uint2*)l;
    }
}

// -------- prep: pack Wu/Wv -> g_w1 (transpose [d][r] -> rows n, k'=d; 3 chunks) --------
__global__ void pack_w1_kernel(const float* __restrict__ Wu,
                               const float* __restrict__ Wv) {
    int e = blockIdx.z & 7;
    int isV = blockIdx.z >> 3;
    const float* W = (isV ? Wv : Wu) + (size_t)e * DD * RR;

    __shared__ float tile[32][33];
    int d0 = blockIdx.x * 32, r0 = blockIdx.y * 32;
    int tid = threadIdx.x;

    int dl = tid >> 3, rl = (tid & 7) * 4;
    float4 v = *(const float4*)(W + (size_t)(d0 + dl) * RR + r0 + rl);
    tile[dl][rl + 0] = v.x; tile[dl][rl + 1] = v.y;
    tile[dl][rl + 2] = v.z; tile[dl][rl + 3] = v.w;
    __syncthreads();

    int dp = (tid & 15) * 2;
#pragma unroll
    for (int rr = tid >> 4; rr < 32; rr += 16) {
        float a = tile[dp][rr], b = tile[dp + 1][rr];
        __nv_bfloat16 ph[2], pl[2];
        split_bf16(a, ph[0], pl[0]);
        split_bf16(b, ph[1], pl[1]);
        int r = r0 + rr;
        int nt = r >> 6;
        int n = (r & 63) + isV * 64;
        size_t base = ((size_t)(e * 4 + nt) * 128 + n) * 3072 + d0 + dp;
        *(uint32_t*)(g_w1 + base)        = *(const uint32_t*)ph;
        *(uint32_t*)(g_w1 + base + 1024) = *(const uint32_t*)pl;
        *(uint32_t*)(g_w1 + base + 2048) = *(const uint32_t*)ph;
    }
}

// -------- prep: pack Wo[e][r][d] -> g_wop[e][d][k'] (3 chunks of r) --------
__global__ void pack_wo_kernel(const float* __restrict__ Wo) {
    int e = blockIdx.z;
    const float* W = Wo + (size_t)e * RR * DD;   // [r][d]

    __shared__ float tile[32][33];               // tile[r][d]
    int d0 = blockIdx.x * 32, r0 = blockIdx.y * 32;
    int tid = threadIdx.x;

    int rl = tid >> 3, dl = (tid & 7) * 4;
    float4 v = *(const float4*)(W + (size_t)(r0 + rl) * DD + d0 + dl);
    tile[rl][dl + 0] = v.x; tile[rl][dl + 1] = v.y;
    tile[rl][dl + 2] = v.z; tile[rl][dl + 3] = v.w;
    __syncthreads();

    int rp = (tid & 15) * 2;
#pragma unroll
    for (int dd = tid >> 4; dd < 32; dd += 16) {
        float a = tile[rp][dd], b = tile[rp + 1][dd];
        __nv_bfloat16 ph[2], pl[2];
        split_bf16(a, ph[0], pl[0]);
        split_bf16(b, ph[1], pl[1]);
        size_t base = ((size_t)e * DD + d0 + dd) * 768 + r0 + rp;
        *(uint32_t*)(g_wop + base)       = *(const uint32_t*)ph;
        *(uint32_t*)(g_wop + base + 256) = *(const uint32_t*)pl;
        *(uint32_t*)(g_wop + base + 512) = *(const uint32_t*)ph;
    }
}

// ==================== pass1: [cnt x 3072] * [3072 x 128] per (e, nt) ====================
// BM=128, BN=128 (cols 0..63 = U, 64..127 = V for r-range [64*nt, 64*nt+64)), BK=64.
#define STAGE 32768                      // A 16KB + B 16KB per stage
#define P1_DSMEM (128 * 132 * 4)         // epilogue C stage (67,584 B) >= 2*STAGE

__global__ __launch_bounds__(256, 1)
void pass1_mma() {
    int e = blockIdx.z;
    int nt = blockIdx.y;
    int cnt = g_count[e];
    int mbase = blockIdx.x * 128;
    if (mbase >= cnt) return;

    extern __shared__ char sm[];
    uint32_t smb = smem_u32(sm);
    __shared__ int   s_sidx[128];
    __shared__ int   s_tok[128];
    __shared__ float s_gate[128];

    int tid = threadIdx.x, lane = tid & 31, wid = tid >> 5;

    if (tid < 128) {
        int slot = mbase + tid;
        bool v = slot < cnt;
        int sidx = v ? g_sidx[e * T_TOT + slot] : 0;
        s_sidx[tid] = sidx;
        s_tok[tid]  = v ? (sidx >> 1) : 0;
        s_gate[tid] = v ? g_gate[e * T_TOT + slot] : 0.f;
    }
    __syncthreads();

    // ---- loader geometry: 2 threads per row (64B halves of 128B row) ----
    int row = tid >> 1, half = tid & 1;
    size_t arow = (size_t)s_tok[row] * DD;
    const __nv_bfloat16* bsrc = g_w1 + ((size_t)(e * 4 + nt) * 128 + row) * 3072 + half * 32;
    uint32_t swo[4];
#pragma unroll
    for (int i = 0; i < 4; i++) swo[i] = sw_off(row, half * 4 + i);

    auto loadA = [&](int it, int s) {
        const __nv_bfloat16* xs = ((it >> 4) == 2) ? g_xl : g_xh;
        const __nv_bfloat16* src = xs + arow + ((it << 6) & 1023) + half * 32;
        uint32_t dst = smb + s * STAGE;
#pragma unroll
        for (int i = 0; i < 4; i++) cp16(dst + swo[i], src + i * 8);
    };
    auto loadB = [&](int it, int s) {
        const __nv_bfloat16* src = bsrc + it * 64;
        uint32_t dst = smb + s * STAGE + 16384;
#pragma unroll
        for (int i = 0; i < 4; i++) cp16(dst + swo[i], src + i * 8);
    };

    // ---- mma geometry ----
    int wm = wid & 1, wn = wid >> 1;        // 2 x 4 warp grid; warptile 64m x 32n
    int rloc = lane & 15, koct = lane >> 4;
    int rx = rloc & 7;
    uint32_t rowA[4], rowB[2];
#pragma unroll
    for (int im = 0; im < 4; im++) rowA[im] = (uint32_t)(wm * 64 + im * 16 + rloc) * 128u;
#pragma unroll
    for (int h = 0; h < 2; h++) rowB[h] = 16384u + (uint32_t)(wn * 32 + h * 16 + rloc) * 128u;

    float c[4][4][4];
#pragma unroll
    for (int i = 0; i < 4; i++)
#pragma unroll
        for (int j = 0; j < 4; j++)
#pragma unroll
            for (int q = 0; q < 4; q++) c[i][j][q] = 0.f;

    const int NIT = 3072 / 64;
    loadA(0, 0); loadB(0, 0); CP_COMMIT();

    for (int it = 0; it < NIT; ++it) {
        int s = it & 1;
        if (it + 1 < NIT) { loadA(it + 1, s ^ 1); loadB(it + 1, s ^ 1); CP_COMMIT(); CP_WAIT1(); }
        else              { CP_WAIT0(); }
        __syncthreads();

        uint32_t sb = smb + s * STAGE;
#pragma unroll
        for (int ks = 0; ks < 4; ks++) {
            uint32_t kx = (uint32_t)(((2 * ks + koct) ^ rx) << 4);
            uint32_t a[4][4], b[2][4];
#pragma unroll
            for (int im = 0; im < 4; im++) ldsm_x4(a[im], sb + rowA[im] + kx);
#pragma unroll
            for (int h = 0; h < 2; h++) ldsm_x4(b[h], sb + rowB[h] + kx);
#pragma unroll
            for (int im = 0; im < 4; im++) {
                mma_bf16(c[im][0], a[im][0], a[im][1], a[im][2], a[im][3], b[0][0], b[0][2]);
                mma_bf16(c[im][1], a[im][0], a[im][1], a[im][2], a[im][3], b[0][1], b[0][3]);
                mma_bf16(c[im][2], a[im][0], a[im][1], a[im][2], a[im][3], b[1][0], b[1][2]);
                mma_bf16(c[im][3], a[im][0], a[im][1], a[im][2], a[im][3], b[1][1], b[1][3]);
            }
        }
        __syncthreads();
    }

    // ---- epilogue: stage C, fuse s = gate * silu(u) * v, store bf16 hi/lo ----
    float* smC = (float*)sm;
#pragma unroll
    for (int im = 0; im < 4; im++) {
        int r1 = wm * 64 + im * 16 + (lane >> 2);
#pragma unroll
        for (int jn = 0; jn < 4; jn++) {
            int cb = wn * 32 + jn * 8 + ((lane & 3) << 1);
            *(float2*)&smC[r1 * 132 + cb]       = make_float2(c[im][jn][0], c[im][jn][1]);
            *(float2*)&smC[(r1 + 8) * 132 + cb] = make_float2(c[im][jn][2], c[im][jn][3]);
        }
    }
    __syncthreads();

    int rr = tid >> 1, seg = tid & 1;
    int slot = mbase + rr;
    if (slot < cnt) {
        int sidx = s_sidx[rr];
        float gate = s_gate[rr];
        size_t ob = (size_t)sidx * RR + nt * 64 + seg * 32;
        const float* uptr = &smC[rr * 132 + seg * 32];
        const float* vptr = uptr + 64;
#pragma unroll
        for (int j = 0; j < 32; j += 2) {
            float u0 = uptr[j], u1 = uptr[j + 1];
            float v0 = vptr[j], v1 = vptr[j + 1];
            float s0 = gate * u0 * v0 / (1.f + __expf(-u0));
            float s1 = gate * u1 * v1 / (1.f + __expf(-u1));
            __nv_bfloat16 h2[2], l2[2];
            split_bf16(s0, h2[0], l2[0]);
            split_bf16(s1, h2[1], l2[1]);
            *(uint32_t*)(g_sh + ob + j) = *(const uint32_t*)h2;
            *(uint32_t*)(g_sl + ob + j) = *(const uint32_t*)l2;
        }
    }
}

// ==================== pass2: [cnt x 768] * [768 x 128] per (e, d-tile) ====================
#define P2_DSMEM (2 * STAGE)

__global__ __launch_bounds__(256, 1)
void pass2_mma(float* __restrict__ out) {
    int e = blockIdx.z;
    int ntile = blockIdx.y;                 // d-base = ntile*128
    int cnt = g_count[e];
    int mbase = blockIdx.x * 128;
    if (mbase >= cnt) return;

    extern __shared__ char sm[];
    uint32_t smb = smem_u32(sm);
    __shared__ int s_row[128];              // sidx (S-row)
    __shared__ int s_tok[128];
    __shared__ int s_val[128];

    int tid = threadIdx.x, lane = tid & 31, wid = tid >> 5;

    if (tid < 128) {
        int slot = mbase + tid;
        bool v = slot < cnt;
        int sidx = v ? g_sidx[e * T_TOT + slot] : 0;
        s_row[tid] = sidx;
        s_tok[tid] = sidx >> 1;
        s_val[tid] = v ? 1 : 0;
    }
    __syncthreads();

    int row = tid >> 1, half = tid & 1;
    size_t arow = (size_t)s_row[row] * RR;
    const __nv_bfloat16* bsrc = g_wop + ((size_t)e * DD + ntile * 128 + row) * 768 + half * 32;
    uint32_t swo[4];
#pragma unroll
    for (int i = 0; i < 4; i++) swo[i] = sw_off(row, half * 4 + i);

    auto loadA = [&](int it, int s) {
        const __nv_bfloat16* xs = ((it >> 2) == 2) ? g_sl : g_sh;
        const __nv_bfloat16* src = xs + arow + ((it << 6) & 255) + half * 32;
        uint32_t dst = smb + s * STAGE;
#pragma unroll
        for (int i = 0; i < 4; i++) cp16(dst + swo[i], src + i * 8);
    };
    auto loadB = [&](int it, int s) {
        const __nv_bfloat16* src = bsrc + it * 64;
        uint32_t dst = smb + s * STAGE + 16384;
#pragma unroll
        for (int i = 0; i < 4; i++) cp16(dst + swo[i], src + i * 8);
    };

    int wm = wid & 1, wn = wid >> 1;
    int rloc = lane & 15, koct = lane >> 4;
    int rx = rloc & 7;
    uint32_t rowA[4], rowB[2];
#pragma unroll
    for (int im = 0; im < 4; im++) rowA[im] = (uint32_t)(wm * 64 + im * 16 + rloc) * 128u;
#pragma unroll
    for (int h = 0; h < 2; h++) rowB[h] = 16384u + (uint32_t)(wn * 32 + h * 16 + rloc) * 128u;

    float c[4][4][4];
#pragma unroll
    for (int i = 0; i < 4; i++)
#pragma unroll
        for (int j = 0; j < 4; j++)
#pragma unroll
            for (int q = 0; q < 4; q++) c[i][j][q] = 0.f;

    const int NIT = 768 / 64;
    loadA(0, 0); loadB(0, 0); CP_COMMIT();

    for (int it = 0; it < NIT; ++it) {
        int s = it & 1;
        if (it + 1 < NIT) { loadA(it + 1, s ^ 1); loadB(it + 1, s ^ 1); CP_COMMIT(); CP_WAIT1(); }
        else              { CP_WAIT0(); }
        __syncthreads();

        uint32_t sb = smb + s * STAGE;
#pragma unroll
        for (int ks = 0; ks < 4; ks++) {
            uint32_t kx = (uint32_t)(((2 * ks + koct) ^ rx) << 4);
            uint32_t a[4][4], b[2][4];
#pragma unroll
            for (int im = 0; im < 4; im++) ldsm_x4(a[im], sb + rowA[im] + kx);
#pragma unroll
            for (int h = 0; h < 2; h++) ldsm_x4(b[h], sb + rowB[h] + kx);
#pragma unroll
            for (int im = 0; im < 4; im++) {
                mma_bf16(c[im][0], a[im][0], a[im][1], a[im][2], a[im][3], b[0][0], b[0][2]);
                mma_bf16(c[im][1], a[im][0], a[im][1], a[im][2], a[im][3], b[0][1], b[0][3]);
                mma_bf16(c[im][2], a[im][0], a[im][1], a[im][2], a[im][3], b[1][0], b[1][2]);
                mma_bf16(c[im][3], a[im][0], a[im][1], a[im][2], a[im][3], b[1][1], b[1][3]);
            }
        }
        __syncthreads();
    }

    // ---- epilogue: atomic accumulate per token ----
#pragma unroll
    for (int im = 0; im < 4; im++) {
        int rl = wm * 64 + im * 16 + (lane >> 2);
        int ok0 = s_val[rl], ok1 = s_val[rl + 8];
        int t0 = s_tok[rl],  t1 = s_tok[rl + 8];
#pragma unroll
        for (int jn = 0; jn < 4; jn++) {
            int col = ntile * 128 + wn * 32 + jn * 8 + ((lane & 3) << 1);
            if (ok0) {
                atomicAdd(out + (size_t)t0 * DD + col,     c[im][jn][0]);
                atomicAdd(out + (size_t)t0 * DD + col + 1, c[im][jn][1]);
            }
            if (ok1) {
                atomicAdd(out + (size_t)t1 * DD + col,     c[im][jn][2]);
                atomicAdd(out + (size_t)t1 * DD + col + 1, c[im][jn][3]);
            }
        }
    }
}

// -------- launch --------
extern "C" void kernel_launch(void* const* d_in, const int* in_sizes, int n_in,
                              void* d_out, int out_size) {
    (void)in_sizes; (void)n_in;
    const float* x  = (const float*)d_in[0];
    const float* gw = (const float*)d_in[1];
    const float* Wu = (const float*)d_in[2];
    const float* Wv = (const float*)d_in[3];
    const float* Wo = (const float*)d_in[4];
    float* out = (float*)d_out;

    cudaFuncSetAttribute(pass1_mma, cudaFuncAttributeMaxDynamicSharedMemorySize, P1_DSMEM);
    cudaFuncSetAttribute(pass2_mma, cudaFuncAttributeMaxDynamicSharedMemorySize, P2_DSMEM);

    int n4 = out_size / 4;
    init_kernel<<<1024, 256>>>((float4*)out, n4);
    router_kernel<<<T_TOT / 8, 256>>>(x, gw);
    split_x_kernel<<<1024, 256>>>((const float4*)x);
    pack_w1_kernel<<<dim3(DD / 32, RR / 32, EE * 2), 256>>>(Wu, Wv);
    pack_wo_kernel<<<dim3(DD / 32, RR / 32, EE), 256>>>(Wo);

    dim3 g1(64, 4, EE);     // M-tiles x r-tiles(64) x experts (early-exit on count)
    pass1_mma<<<g1, 256, P1_DSMEM>>>();

    dim3 g2(64, 8, EE);     // M-tiles x d-tiles(128) x experts
    pass2_mma<<<g2, 256, P2_DSMEM>>>(out);
}

// round 8
// speedup vs baseline: 1.5429x; 1.0315x over previous
#include <cuda_runtime.h>
#include <cuda_bf16.h>
#include <math.h>
#include <stdint.h>

// Problem constants
#define T_TOT 8192   // B*N tokens
#define DD    1024
#define EE    8
#define RR    256
#define NSLOT (T_TOT * 2)

// -------- scratch (__device__ globals; no allocations allowed) --------
__device__ int   g_count[EE];
__device__ int   g_sidx[EE * T_TOT];          // sidx = token*2 + k
__device__ float g_gate[EE * T_TOT];
__device__ __nv_bfloat16 g_xh[T_TOT * DD];    // x hi/lo split
__device__ __nv_bfloat16 g_xl[T_TOT * DD];
__device__ __nv_bfloat16 g_sh[NSLOT * RR];    // s = gate*silu(u)*v hi/lo
__device__ __nv_bfloat16 g_sl[NSLOT * RR];
__device__ float g_Y[NSLOT * DD];             // per-slot down-proj output (64 MB)
// pass1 B packed: [e][nt(4)][n(128)][k(2048)]; n<64: Wu row 64nt+n, else Wv row 64nt+n-64
// k chunks: [0,1024)=hi, [1024,2048)=lo
__device__ __nv_bfloat16 g_w1[EE * 4 * 128 * 2048];
// pass2 B packed: [e][d(1024)][k(512)]; k chunks: [0,256)=Wo hi, [256,512)=lo
__device__ __nv_bfloat16 g_wop[EE * DD * 512];

// -------- PTX helpers (base sm_103 features only) --------
__device__ __forceinline__ uint32_t smem_u32(const void* p) {
    uint32_t a;
    asm("{ .reg .u64 t; cvta.to.shared.u64 t, %1; cvt.u32.u64 %0, t; }" : "=r"(a) : "l"(p));
    return a;
}
__device__ __forceinline__ void cp16(uint32_t dst, const void* src) {
    asm volatile("cp.async.cg.shared.global [%0], [%1], 16;" :: "r"(dst), "l"(src));
}
#define CP_COMMIT() asm volatile("cp.async.commit_group;" ::: "memory")
#define CP_WAIT1()  asm volatile("cp.async.wait_group 1;" ::: "memory")
#define CP_WAIT0()  asm volatile("cp.async.wait_group 0;" ::: "memory")

__device__ __forceinline__ void ldsm_x4(uint32_t r[4], uint32_t addr) {
    asm volatile("ldmatrix.sync.aligned.m8n8.x4.shared.b16 {%0,%1,%2,%3}, [%4];"
                 : "=r"(r[0]), "=r"(r[1]), "=r"(r[2]), "=r"(r[3]) : "r"(addr));
}
__device__ __forceinline__ void mma_bf16(float c[4],
                                         const uint32_t a[4],
                                         uint32_t b0, uint32_t b1) {
    asm("mma.sync.aligned.m16n8k16.row.col.f32.bf16.bf16.f32 "
        "{%0,%1,%2,%3}, {%4,%5,%6,%7}, {%8,%9}, {%0,%1,%2,%3};"
        : "+f"(c[0]), "+f"(c[1]), "+f"(c[2]), "+f"(c[3])
        : "r"(a[0]), "r"(a[1]), "r"(a[2]), "r"(a[3]), "r"(b0), "r"(b1));
}
// SW128 swizzle for 128B rows: byte offset for (row, 16B-group g)
__device__ __forceinline__ uint32_t sw_off(int row, int g) {
    return (uint32_t)row * 128u + (uint32_t)((g ^ (row & 7)) << 4);
}
__device__ __forceinline__ void split_bf16(float v, __nv_bfloat16& h, __nv_bfloat16& l) {
    h = __float2bfloat16_rn(v);
    l = __float2bfloat16_rn(v - __bfloat162float(h));
}

// -------- init: zero counters only (out fully overwritten by combine) --------
__global__ void init_kernel() {
    if (threadIdx.x < EE) g_count[threadIdx.x] = 0;
}

// -------- router: one warp per token --------
__global__ void router_kernel(const float* __restrict__ x,
                              const float* __restrict__ gw) {
    int warp = (blockIdx.x * blockDim.x + threadIdx.x) >> 5;
    int lane = threadIdx.x & 31;
    if (warp >= T_TOT) return;
    const float* xr = x + (size_t)warp * DD;

    float acc[EE];
#pragma unroll
    for (int e = 0; e < EE; e++) acc[e] = 0.f;

    for (int d = lane * 4; d < DD; d += 32 * 4) {
        float4 xv = *(const float4*)(xr + d);
        const float* xp = (const float*)&xv;
#pragma unroll
        for (int j = 0; j < 4; j++) {
            float xs = xp[j];
            float4 g0 = *(const float4*)(gw + (size_t)(d + j) * EE);
            float4 g1 = *(const float4*)(gw + (size_t)(d + j) * EE + 4);
            acc[0] += xs * g0.x; acc[1] += xs * g0.y;
            acc[2] += xs * g0.z; acc[3] += xs * g0.w;
            acc[4] += xs * g1.x; acc[5] += xs * g1.y;
            acc[6] += xs * g1.z; acc[7] += xs * g1.w;
        }
    }
#pragma unroll
    for (int e = 0; e < EE; e++)
#pragma unroll
        for (int off = 16; off; off >>= 1)
            acc[e] += __shfl_xor_sync(0xFFFFFFFFu, acc[e], off);

    if (lane == 0) {
        int i0 = 0; float v0 = acc[0];
#pragma unroll
        for (int e = 1; e < EE; e++) if (acc[e] > v0) { v0 = acc[e]; i0 = e; }
        int i1 = -1; float v1 = -INFINITY;
#pragma unroll
        for (int e = 0; e < EE; e++) if (e != i0 && acc[e] > v1) { v1 = acc[e]; i1 = e; }
        float w0 = 1.f / (1.f + expf(v1 - v0));
        float w1 = 1.f - w0;
        int p0 = atomicAdd(&g_count[i0], 1);
        g_sidx[i0 * T_TOT + p0] = warp * 2 + 0;
        g_gate[i0 * T_TOT + p0] = w0;
        int p1 = atomicAdd(&g_count[i1], 1);
        g_sidx[i1 * T_TOT + p1] = warp * 2 + 1;
        g_gate[i1 * T_TOT + p1] = w1;
    }
}

// -------- prep: split x into bf16 hi/lo --------
__global__ void split_x_kernel(const float4* __restrict__ x4) {
    int n4 = T_TOT * DD / 4;
    int stride = gridDim.x * blockDim.x;
    for (int i = blockIdx.x * blockDim.x + threadIdx.x; i < n4; i += stride) {
        float4 v = x4[i];
        const float* vp = (const float*)&v;
        __nv_bfloat16 h[4], l[4];
#pragma unroll
        for (int j = 0; j < 4; j++) split_bf16(vp[j], h[j], l[j]);
        *(uint2*)(g_xh + (size_t)i * 4) = *(const uint2*)h;
        *(uint2*)(g_xl + (size_t)i * 4) = *(const uint2*)l;
    }
}

// -------- prep: pack Wu/Wv -> g_w1 (transpose [d][r] -> rows n, k=d; hi|lo) --------
__global__ void pack_w1_kernel(const float* __restrict__ Wu,
                               const float* __restrict__ Wv) {
    int e = blockIdx.z & 7;
    int isV = blockIdx.z >> 3;
    const float* W = (isV ? Wv : Wu) + (size_t)e * DD * RR;

    __shared__ float tile[32][33];
    int d0 = blockIdx.x * 32, r0 = blockIdx.y * 32;
    int tid = threadIdx.x;

    int dl = tid >> 3, rl = (tid & 7) * 4;
    float4 v = *(const float4*)(W + (size_t)(d0 + dl) * RR + r0 + rl);
    tile[dl][rl + 0] = v.x; tile[dl][rl + 1] = v.y;
    tile[dl][rl + 2] = v.z; tile[dl][rl + 3] = v.w;
    __syncthreads();

    int dp = (tid & 15) * 2;
#pragma unroll
    for (int rr = tid >> 4; rr < 32; rr += 16) {
        float a = tile[dp][rr], b = tile[dp + 1][rr];
        __nv_bfloat16 ph[2], pl[2];
        split_bf16(a, ph[0], pl[0]);
        split_bf16(b, ph[1], pl[1]);
        int r = r0 + rr;
        int nt = r >> 6;
        int n = (r & 63) + isV * 64;
        size_t base = ((size_t)(e * 4 + nt) * 128 + n) * 2048 + d0 + dp;
        *(uint32_t*)(g_w1 + base)        = *(const uint32_t*)ph;
        *(uint32_t*)(g_w1 + base + 1024) = *(const uint32_t*)pl;
    }
}

// -------- prep: pack Wo[e][r][d] -> g_wop[e][d][k] (hi|lo) --------
__global__ void pack_wo_kernel(const float* __restrict__ Wo) {
    int e = blockIdx.z;
    const float* W = Wo + (size_t)e * RR * DD;   // [r][d]

    __shared__ float tile[32][33];               // tile[r][d]
    int d0 = blockIdx.x * 32, r0 = blockIdx.y * 32;
    int tid = threadIdx.x;

    int rl = tid >> 3, dl = (tid & 7) * 4;
    float4 v = *(const float4*)(W + (size_t)(r0 + rl) * DD + d0 + dl);
    tile[rl][dl + 0] = v.x; tile[rl][dl + 1] = v.y;
    tile[rl][dl + 2] = v.z; tile[rl][dl + 3] = v.w;
    __syncthreads();

    int rp = (tid & 15) * 2;
#pragma unroll
    for (int dd = tid >> 4; dd < 32; dd += 16) {
        float a = tile[rp][dd], b = tile[rp + 1][dd];
        __nv_bfloat16 ph[2], pl[2];
        split_bf16(a, ph[0], pl[0]);
        split_bf16(b, ph[1], pl[1]);
        size_t base = ((size_t)e * DD + d0 + dd) * 512 + r0 + rp;
        *(uint32_t*)(g_wop + base)       = *(const uint32_t*)ph;
        *(uint32_t*)(g_wop + base + 256) = *(const uint32_t*)pl;
    }
}

// ==================== shared-operand 3-term MMA core ====================
// Stage layout (64 KB): [Ah 16K][Al 16K][Bh 16K][Bl 16K]; 2 stages = 128 KB.
// C += Ah*Bh + Al*Bh + Ah*Bl   (lo*lo dropped)
#define TILE16 16384
#define STAGE  65536
#define MMA_DSMEM (2 * STAGE)

struct MmaCore {
    uint32_t rowA[4];   // byte offsets within A tile
    uint32_t rowB[2];   // byte offsets within B tile
    int koct, rx;
};
__device__ __forceinline__ void mma_core_init(MmaCore& mc, int wid, int lane) {
    int wm = wid & 1, wn = wid >> 1;
    int rloc = lane & 15;
    mc.koct = lane >> 4;
    mc.rx = rloc & 7;
#pragma unroll
    for (int im = 0; im < 4; im++) mc.rowA[im] = (uint32_t)(wm * 64 + im * 16 + rloc) * 128u;
#pragma unroll
    for (int h = 0; h < 2; h++) mc.rowB[h] = (uint32_t)(wn * 32 + h * 16 + rloc) * 128u;
}
__device__ __forceinline__ void mma_chunk(const MmaCore& mc, uint32_t sb, float c[4][4][4]) {
#pragma unroll
    for (int ks = 0; ks < 4; ks++) {
        uint32_t kx = (uint32_t)(((2 * ks + mc.koct) ^ mc.rx) << 4);
        uint32_t ah[4][4], al[4][4], bh[2][4], bl[2][4];
#pragma unroll
        for (int im = 0; im < 4; im++) {
            ldsm_x4(ah[im], sb + mc.rowA[im] + kx);
            ldsm_x4(al[im], sb + TILE16 + mc.rowA[im] + kx);
        }
#pragma unroll
        for (int h = 0; h < 2; h++) {
            ldsm_x4(bh[h], sb + 2 * TILE16 + mc.rowB[h] + kx);
            ldsm_x4(bl[h], sb + 3 * TILE16 + mc.rowB[h] + kx);
        }
#pragma unroll
        for (int im = 0; im < 4; im++) {
            mma_bf16(c[im][0], ah[im], bh[0][0], bh[0][2]);
            mma_bf16(c[im][1], ah[im], bh[0][1], bh[0][3]);
            mma_bf16(c[im][2], ah[im], bh[1][0], bh[1][2]);
            mma_bf16(c[im][3], ah[im], bh[1][1], bh[1][3]);
            mma_bf16(c[im][0], al[im], bh[0][0], bh[0][2]);
            mma_bf16(c[im][1], al[im], bh[0][1], bh[0][3]);
            mma_bf16(c[im][2], al[im], bh[1][0], bh[1][2]);
            mma_bf16(c[im][3], al[im], bh[1][1], bh[1][3]);
            mma_bf16(c[im][0], ah[im], bl[0][0], bl[0][2]);
            mma_bf16(c[im][1], ah[im], bl[0][1], bl[0][3]);
            mma_bf16(c[im][2], ah[im], bl[1][0], bl[1][2]);
            mma_bf16(c[im][3], ah[im], bl[1][1], bl[1][3]);
        }
    }
}

// ==================== pass1: [cnt x (1024 hi/lo)] * W1 -> U|V, fuse SwiGLU ====================
__global__ __launch_bounds__(256, 1)
void pass1_mma() {
    int e = blockIdx.z;
    int nt = blockIdx.y;
    int cnt = g_count[e];
    int mbase = blockIdx.x * 128;
    if (mbase >= cnt) return;

    extern __shared__ char sm[];
    uint32_t smb = smem_u32(sm);
    __shared__ int   s_sidx[128];
    __shared__ int   s_tok[128];
    __shared__ float s_gate[128];

    int tid = threadIdx.x, lane = tid & 31, wid = tid >> 5;

    if (tid < 128) {
        int slot = mbase + tid;
        bool v = slot < cnt;
        int sidx = v ? g_sidx[e * T_TOT + slot] : 0;
        s_sidx[tid] = sidx;
        s_tok[tid]  = v ? (sidx >> 1) : 0;
        s_gate[tid] = v ? g_gate[e * T_TOT + slot] : 0.f;
    }
    __syncthreads();

    // loader: 2 threads per row (64B halves of the 128B tile row)
    int row = tid >> 1, half = tid & 1;
    size_t arow = (size_t)s_tok[row] * DD + half * 32;
    const __nv_bfloat16* bsrc = g_w1 + ((size_t)(e * 4 + nt) * 128 + row) * 2048 + half * 32;
    uint32_t swo[4];
#pragma unroll
    for (int i = 0; i < 4; i++) swo[i] = sw_off(row, half * 4 + i);

    auto loadStage = [&](int kc, int s) {
        uint32_t dst = smb + s * STAGE;
        const __nv_bfloat16* ah = g_xh + arow + kc * 64;
        const __nv_bfloat16* al = g_xl + arow + kc * 64;
        const __nv_bfloat16* bh = bsrc + kc * 64;
        const __nv_bfloat16* bl = bsrc + 1024 + kc * 64;
#pragma unroll
        for (int i = 0; i < 4; i++) {
            cp16(dst + swo[i],              ah + i * 8);
            cp16(dst + TILE16 + swo[i],     al + i * 8);
            cp16(dst + 2 * TILE16 + swo[i], bh + i * 8);
            cp16(dst + 3 * TILE16 + swo[i], bl + i * 8);
        }
    };

    MmaCore mc;
    mma_core_init(mc, wid, lane);
    int wm = wid & 1, wn = wid >> 1;

    float c[4][4][4];
#pragma unroll
    for (int i = 0; i < 4; i++)
#pragma unroll
        for (int j = 0; j < 4; j++)
#pragma unroll
            for (int q = 0; q < 4; q++) c[i][j][q] = 0.f;

    const int NIT = DD / 64;   // 16
    loadStage(0, 0); CP_COMMIT();
    for (int it = 0; it < NIT; ++it) {
        int s = it & 1;
        if (it + 1 < NIT) { loadStage(it + 1, s ^ 1); CP_COMMIT(); CP_WAIT1(); }
        else              { CP_WAIT0(); }
        __syncthreads();
        mma_chunk(mc, smb + s * STAGE, c);
        __syncthreads();
    }

    // epilogue: stage C in smem, fuse s = gate * silu(u) * v, store bf16 hi/lo
    float* smC = (float*)sm;
#pragma unroll
    for (int im = 0; im < 4; im++) {
        int r1 = wm * 64 + im * 16 + (lane >> 2);
#pragma unroll
        for (int jn = 0; jn < 4; jn++) {
            int cb = wn * 32 + jn * 8 + ((lane & 3) << 1);
            *(float2*)&smC[r1 * 132 + cb]       = make_float2(c[im][jn][0], c[im][jn][1]);
            *(float2*)&smC[(r1 + 8) * 132 + cb] = make_float2(c[im][jn][2], c[im][jn][3]);
        }
    }
    __syncthreads();

    int rr = tid >> 1, seg = tid & 1;
    int slot = mbase + rr;
    if (slot < cnt) {
        int sidx = s_sidx[rr];
        float gate = s_gate[rr];
        size_t ob = (size_t)sidx * RR + nt * 64 + seg * 32;
        const float* uptr = &smC[rr * 132 + seg * 32];
        const float* vptr = uptr + 64;
#pragma unroll
        for (int j = 0; j < 32; j += 2) {
            float u0 = uptr[j], u1 = uptr[j + 1];
            float v0 = vptr[j], v1 = vptr[j + 1];
            float s0 = gate * u0 * v0 / (1.f + __expf(-u0));
            float s1 = gate * u1 * v1 / (1.f + __expf(-u1));
            __nv_bfloat16 h2[2], l2[2];
            split_bf16(s0, h2[0], l2[0]);
            split_bf16(s1, h2[1], l2[1]);
            *(uint32_t*)(g_sh + ob + j) = *(const uint32_t*)h2;
            *(uint32_t*)(g_sl + ob + j) = *(const uint32_t*)l2;
        }
    }
}

// ==================== pass2: [cnt x (256 hi/lo)] * Wo -> g_Y (plain stores) ====================
__global__ __launch_bounds__(256, 1)
void pass2_mma() {
    int e = blockIdx.z;
    int ntile = blockIdx.y;
    int cnt = g_count[e];
    int mbase = blockIdx.x * 128;
    if (mbase >= cnt) return;

    extern __shared__ char sm[];
    uint32_t smb = smem_u32(sm);
    __shared__ int s_row[128];
    __shared__ int s_val[128];

    int tid = threadIdx.x, lane = tid & 31, wid = tid >> 5;

    if (tid < 128) {
        int slot = mbase + tid;
        bool v = slot < cnt;
        s_row[tid] = v ? g_sidx[e * T_TOT + slot] : 0;
        s_val[tid] = v ? 1 : 0;
    }
    __syncthreads();

    int row = tid >> 1, half = tid & 1;
    size_t arow = (size_t)s_row[row] * RR + half * 32;
    const __nv_bfloat16* bsrc = g_wop + ((size_t)e * DD + ntile * 128 + row) * 512 + half * 32;
    uint32_t swo[4];
#pragma unroll
    for (int i = 0; i < 4; i++) swo[i] = sw_off(row, half * 4 + i);

    auto loadStage = [&](int kc, int s) {
        uint32_t dst = smb + s * STAGE;
        const __nv_bfloat16* ah = g_sh + arow + kc * 64;
        const __nv_bfloat16* al = g_sl + arow + kc * 64;
        const __nv_bfloat16* bh = bsrc + kc * 64;
        const __nv_bfloat16* bl = bsrc + 256 + kc * 64;
#pragma unroll
        for (int i = 0; i < 4; i++) {
            cp16(dst + swo[i],              ah + i * 8);
            cp16(dst + TILE16 + swo[i],     al + i * 8);
            cp16(dst + 2 * TILE16 + swo[i], bh + i * 8);
            cp16(dst + 3 * TILE16 + swo[i], bl + i * 8);
        }
    };

    MmaCore mc;
    mma_core_init(mc, wid, lane);
    int wm = wid & 1, wn = wid >> 1;

    float c[4][4][4];
#pragma unroll
    for (int i = 0; i < 4; i++)
#pragma unroll
        for (int j = 0; j < 4; j++)
#pragma unroll
            for (int q = 0; q < 4; q++) c[i][j][q] = 0.f;

    const int NIT = RR / 64;   // 4
    loadStage(0, 0); CP_COMMIT();
    for (int it = 0; it < NIT; ++it) {
        int s = it & 1;
        if (it + 1 < NIT) { loadStage(it + 1, s ^ 1); CP_COMMIT(); CP_WAIT1(); }
        else              { CP_WAIT0(); }
        __syncthreads();
        mma_chunk(mc, smb + s * STAGE, c);
        __syncthreads();
    }

    // epilogue: plain float2 stores into per-slot Y rows
#pragma unroll
    for (int im = 0; im < 4; im++) {
        int rl = wm * 64 + im * 16 + (lane >> 2);
        int ok0 = s_val[rl], ok1 = s_val[rl + 8];
        int r0 = s_row[rl],  r1 = s_row[rl + 8];
#pragma unroll
        for (int jn = 0; jn < 4; jn++) {
            int col = ntile * 128 + wn * 32 + jn * 8 + ((lane & 3) << 1);
            if (ok0) *(float2*)(g_Y + (size_t)r0 * DD + col) = make_float2(c[im][jn][0], c[im][jn][1]);
            if (ok1) *(float2*)(g_Y + (size_t)r1 * DD + col) = make_float2(c[im][jn][2], c[im][jn][3]);
        }
    }
}

// -------- combine: out[t] = Y[2t] + Y[2t+1] --------
__global__ void combine_kernel(float4* __restrict__ out4) {
    const int D4 = DD / 4;
    int n = T_TOT * D4;
    int stride = gridDim.x * blockDim.x;
    const float4* Y4 = (const float4*)g_Y;
    for (int i = blockIdx.x * blockDim.x + threadIdx.x; i < n; i += stride) {
        int t = i / D4, d4 = i - t * D4;
        float4 a = Y4[(size_t)(2 * t) * D4 + d4];
        float4 b = Y4[(size_t)(2 * t + 1) * D4 + d4];
        out4[i] = make_float4(a.x + b.x, a.y + b.y, a.z + b.z, a.w + b.w);
    }
}

// -------- launch --------
extern "C" void kernel_launch(void* const* d_in, const int* in_sizes, int n_in,
                              void* d_out, int out_size) {
    (void)in_sizes; (void)n_in; (void)out_size;
    const float* x  = (const float*)d_in[0];
    const float* gw = (const float*)d_in[1];
    const float* Wu = (const float*)d_in[2];
    const float* Wv = (const float*)d_in[3];
    const float* Wo = (const float*)d_in[4];
    float* out = (float*)d_out;

    cudaFuncSetAttribute(pass1_mma, cudaFuncAttributeMaxDynamicSharedMemorySize, MMA_DSMEM);
    cudaFuncSetAttribute(pass2_mma, cudaFuncAttributeMaxDynamicSharedMemorySize, MMA_DSMEM);

    init_kernel<<<1, 32>>>();
    router_kernel<<<T_TOT / 8, 256>>>(x, gw);
    split_x_kernel<<<1024, 256>>>((const float4*)x);
    pack_w1_kernel<<<dim3(DD / 32, RR / 32, EE * 2), 256>>>(Wu, Wv);
    pack_wo_kernel<<<dim3(DD / 32, RR / 32, EE), 256>>>(Wo);

    dim3 g1(64, 4, EE);     // M-tiles x r-tiles(64) x experts (early-exit on count)
    pass1_mma<<<g1, 256, MMA_DSMEM>>>();

    dim3 g2(64, 8, EE);     // M-tiles x d-tiles(128) x experts
    pass2_mma<<<g2, 256, MMA_DSMEM>>>();

    combine_kernel<<<1024, 256>>>((float4*)out);
}

// round 9
// speedup vs baseline: 1.9826x; 1.2849x over previous
#include <cuda_runtime.h>
#include <cuda_fp16.h>
#include <math.h>
#include <stdint.h>

// Problem constants
#define T_TOT 8192   // B*N tokens
#define DD    1024
#define EE    8
#define RR    256
#define NSLOT (T_TOT * 2)

// -------- scratch (__device__ globals; no allocations allowed) --------
__device__ int   g_count[EE];
__device__ int   g_sidx[EE * T_TOT];          // sidx = token*2 + k
__device__ float g_gate[EE * T_TOT];
__device__ __half g_xh[T_TOT * DD];           // x hi/lo split (fp16)
__device__ __half g_xl[T_TOT * DD];
__device__ __half g_sh[NSLOT * RR];           // s = gate*silu(u)*v hi/lo
__device__ __half g_sl[NSLOT * RR];
__device__ float g_Y[NSLOT * DD];             // per-slot down-proj output (64 MB)
// pass1 B packed (fp16, hi only): [e][nt(2)][n(256)][k(1024)]
//   n<128: Wu row 128*nt+n ; n>=128: Wv row 128*nt + (n-128)
__device__ __half g_w1[EE * 2 * 256 * 1024];
// pass2 B packed (fp16, hi only): [e][d(1024)][k(256)]
__device__ __half g_wop[EE * DD * 256];

// -------- PTX helpers (base sm_103 features only) --------
__device__ __forceinline__ uint32_t smem_u32(const void* p) {
    uint32_t a;
    asm("{ .reg .u64 t; cvta.to.shared.u64 t, %1; cvt.u32.u64 %0, t; }" : "=r"(a) : "l"(p));
    return a;
}
__device__ __forceinline__ void cp16(uint32_t dst, const void* src) {
    asm volatile("cp.async.cg.shared.global [%0], [%1], 16;" :: "r"(dst), "l"(src));
}
#define CP_COMMIT() asm volatile("cp.async.commit_group;" ::: "memory")
#define CP_WAIT1()  asm volatile("cp.async.wait_group 1;" ::: "memory")
#define CP_WAIT0()  asm volatile("cp.async.wait_group 0;" ::: "memory")

__device__ __forceinline__ void ldsm_x4(uint32_t r[4], uint32_t addr) {
    asm volatile("ldmatrix.sync.aligned.m8n8.x4.shared.b16 {%0,%1,%2,%3}, [%4];"
                 : "=r"(r[0]), "=r"(r[1]), "=r"(r[2]), "=r"(r[3]) : "r"(addr));
}
__device__ __forceinline__ void mma_f16(float c[4],
                                        const uint32_t a[4],
                                        uint32_t b0, uint32_t b1) {
    asm("mma.sync.aligned.m16n8k16.row.col.f32.f16.f16.f32 "
        "{%0,%1,%2,%3}, {%4,%5,%6,%7}, {%8,%9}, {%0,%1,%2,%3};"
        : "+f"(c[0]), "+f"(c[1]), "+f"(c[2]), "+f"(c[3])
        : "r"(a[0]), "r"(a[1]), "r"(a[2]), "r"(a[3]), "r"(b0), "r"(b1));
}
// SW128 swizzle for 128B rows: byte offset for (row, 16B-group g)
__device__ __forceinline__ uint32_t sw_off(int row, int g) {
    return (uint32_t)row * 128u + (uint32_t)((g ^ (row & 7)) << 4);
}
__device__ __forceinline__ void split_f16(float v, __half& h, __half& l) {
    h = __float2half_rn(v);
    l = __float2half_rn(v - __half2float(h));
}

// -------- init: zero counters --------
__global__ void init_kernel() {
    if (threadIdx.x < EE) g_count[threadIdx.x] = 0;
}

// -------- router + x split (fused): one warp per token, then grid-stride split --------
__global__ void router_split_kernel(const float* __restrict__ x,
                                    const float* __restrict__ gw) {
    int warp = (blockIdx.x * blockDim.x + threadIdx.x) >> 5;
    int lane = threadIdx.x & 31;
    {
        const float* xr = x + (size_t)warp * DD;
        float acc[EE];
#pragma unroll
        for (int e = 0; e < EE; e++) acc[e] = 0.f;
        for (int d = lane * 4; d < DD; d += 32 * 4) {
            float4 xv = *(const float4*)(xr + d);
            const float* xp = (const float*)&xv;
#pragma unroll
            for (int j = 0; j < 4; j++) {
                float xs = xp[j];
                float4 g0 = *(const float4*)(gw + (size_t)(d + j) * EE);
                float4 g1 = *(const float4*)(gw + (size_t)(d + j) * EE + 4);
                acc[0] += xs * g0.x; acc[1] += xs * g0.y;
                acc[2] += xs * g0.z; acc[3] += xs * g0.w;
                acc[4] += xs * g1.x; acc[5] += xs * g1.y;
                acc[6] += xs * g1.z; acc[7] += xs * g1.w;
            }
        }
#pragma unroll
        for (int e = 0; e < EE; e++)
#pragma unroll
            for (int off = 16; off; off >>= 1)
                acc[e] += __shfl_xor_sync(0xFFFFFFFFu, acc[e], off);

        if (lane == 0) {
            int i0 = 0; float v0 = acc[0];
#pragma unroll
            for (int e = 1; e < EE; e++) if (acc[e] > v0) { v0 = acc[e]; i0 = e; }
            int i1 = -1; float v1 = -INFINITY;
#pragma unroll
            for (int e = 0; e < EE; e++) if (e != i0 && acc[e] > v1) { v1 = acc[e]; i1 = e; }
            float w0 = 1.f / (1.f + expf(v1 - v0));
            float w1 = 1.f - w0;
            int p0 = atomicAdd(&g_count[i0], 1);
            g_sidx[i0 * T_TOT + p0] = warp * 2 + 0;
            g_gate[i0 * T_TOT + p0] = w0;
            int p1 = atomicAdd(&g_count[i1], 1);
            g_sidx[i1 * T_TOT + p1] = warp * 2 + 1;
            g_gate[i1 * T_TOT + p1] = w1;
        }
    }
    // ---- x hi/lo split (grid-stride over float4) ----
    const float4* x4 = (const float4*)x;
    int n4 = T_TOT * DD / 4;
    int stride = gridDim.x * blockDim.x;
    for (int i = blockIdx.x * blockDim.x + threadIdx.x; i < n4; i += stride) {
        float4 v = x4[i];
        const float* vp = (const float*)&v;
        __half h[4], l[4];
#pragma unroll
        for (int j = 0; j < 4; j++) split_f16(vp[j], h[j], l[j]);
        *(uint2*)(g_xh + (size_t)i * 4) = *(const uint2*)h;
        *(uint2*)(g_xl + (size_t)i * 4) = *(const uint2*)l;
    }
}

// -------- prep: pack Wu/Wv -> g_w1 (transpose [d][r] -> [n][k=d], fp16 hi) --------
__global__ void pack_w1_kernel(const float* __restrict__ Wu,
                               const float* __restrict__ Wv) {
    int e = blockIdx.z & 7;
    int isV = blockIdx.z >> 3;
    const float* W = (isV ? Wv : Wu) + (size_t)e * DD * RR;

    __shared__ float tile[32][33];
    int d0 = blockIdx.x * 32, r0 = blockIdx.y * 32;
    int tid = threadIdx.x;

    int dl = tid >> 3, rl = (tid & 7) * 4;
    float4 v = *(const float4*)(W + (size_t)(d0 + dl) * RR + r0 + rl);
    tile[dl][rl + 0] = v.x; tile[dl][rl + 1] = v.y;
    tile[dl][rl + 2] = v.z; tile[dl][rl + 3] = v.w;
    __syncthreads();

    int dp = (tid & 15) * 2;
#pragma unroll
    for (int rr = tid >> 4; rr < 32; rr += 16) {
        __half p2[2];
        p2[0] = __float2half_rn(tile[dp][rr]);
        p2[1] = __float2half_rn(tile[dp + 1][rr]);
        int r = r0 + rr;
        int nt = r >> 7;
        int n = (r & 127) + isV * 128;
        size_t base = ((size_t)(e * 2 + nt) * 256 + n) * 1024 + d0 + dp;
        *(uint32_t*)(g_w1 + base) = *(const uint32_t*)p2;
    }
}

// -------- prep: pack Wo[e][r][d] -> g_wop[e][d][k=r] (fp16 hi) --------
__global__ void pack_wo_kernel(const float* __restrict__ Wo) {
    int e = blockIdx.z;
    const float* W = Wo + (size_t)e * RR * DD;   // [r][d]

    __shared__ float tile[32][33];               // tile[r][d]
    int d0 = blockIdx.x * 32, r0 = blockIdx.y * 32;
    int tid = threadIdx.x;

    int rl = tid >> 3, dl = (tid & 7) * 4;
    float4 v = *(const float4*)(W + (size_t)(r0 + rl) * DD + d0 + dl);
    tile[rl][dl + 0] = v.x; tile[rl][dl + 1] = v.y;
    tile[rl][dl + 2] = v.z; tile[rl][dl + 3] = v.w;
    __syncthreads();

    int rp = (tid & 15) * 2;
#pragma unroll
    for (int dd = tid >> 4; dd < 32; dd += 16) {
        __half p2[2];
        p2[0] = __float2half_rn(tile[rp][dd]);
        p2[1] = __float2half_rn(tile[rp + 1][dd]);
        size_t base = ((size_t)e * DD + d0 + dd) * 256 + r0 + rp;
        *(uint32_t*)(g_wop + base) = *(const uint32_t*)p2;
    }
}

// ==================== 2-term fp16 MMA core ====================
// Stage (64 KB): [Ah 16K][Al 16K][B 32K]; 2 stages = 128 KB.
// BM=128, BN=256, BK=64. 8 warps as 2(m) x 4(n); warptile 64m x 64n.
// C += Ah*B + Al*B   (A = Ah + Al exactly; B rounded once to fp16)
#define TILEA  16384
#define BOFF   32768
#define STAGE  65536
#define CPAD   260
#define MMA_DSMEM (128 * CPAD * 4)   // 133,120 B >= 2*STAGE (131,072)

struct MmaCore {
    uint32_t rowA[4];   // byte offsets within A tile
    uint32_t rowB[4];   // byte offsets within B tile
    int koct, rx;
};
__device__ __forceinline__ void mma_core_init(MmaCore& mc, int wid, int lane) {
    int wm = wid & 1, wn = wid >> 1;
    int rloc = lane & 15;
    mc.koct = lane >> 4;
    mc.rx = rloc & 7;
#pragma unroll
    for (int im = 0; im < 4; im++) mc.rowA[im] = (uint32_t)(wm * 64 + im * 16 + rloc) * 128u;
#pragma unroll
    for (int h = 0; h < 4; h++) mc.rowB[h] = (uint32_t)(wn * 64 + h * 16 + rloc) * 128u;
}
__device__ __forceinline__ void mma_chunk(const MmaCore& mc, uint32_t sb, float c[4][8][4]) {
#pragma unroll
    for (int ks = 0; ks < 4; ks++) {
        uint32_t kx = (uint32_t)(((2 * ks + mc.koct) ^ mc.rx) << 4);
        uint32_t ah[4][4], al[4][4];
#pragma unroll
        for (int im = 0; im < 4; im++) {
            ldsm_x4(ah[im], sb + mc.rowA[im] + kx);
            ldsm_x4(al[im], sb + TILEA + mc.rowA[im] + kx);
        }
#pragma unroll
        for (int h = 0; h < 4; h++) {
            uint32_t b[4];
            ldsm_x4(b, sb + BOFF + mc.rowB[h] + kx);
            // hi terms (8 independent MMAs), then lo terms — avoids back-to-back RAW on c
#pragma unroll
            for (int im = 0; im < 4; im++) {
                mma_f16(c[im][2 * h],     ah[im], b[0], b[2]);
                mma_f16(c[im][2 * h + 1], ah[im], b[1], b[3]);
            }
#pragma unroll
            for (int im = 0; im < 4; im++) {
                mma_f16(c[im][2 * h],     al[im], b[0], b[2]);
                mma_f16(c[im][2 * h + 1], al[im], b[1], b[3]);
            }
        }
    }
}

// ==================== pass1: slots x (D hi/lo) * W1 -> U|V, fuse SwiGLU ====================
__global__ __launch_bounds__(256, 1)
void pass1_mma() {
    int e = blockIdx.z;
    int nt = blockIdx.y;                 // r-halves: cols 0..127 = U rows 128nt.., 128..255 = V
    int cnt = g_count[e];
    int mbase = blockIdx.x * 128;
    if (mbase >= cnt) return;

    extern __shared__ char sm[];
    uint32_t smb = smem_u32(sm);
    __shared__ int   s_sidx[128];
    __shared__ int   s_tok[128];
    __shared__ float s_gate[128];

    int tid = threadIdx.x, lane = tid & 31, wid = tid >> 5;

    if (tid < 128) {
        int slot = mbase + tid;
        bool v = slot < cnt;
        int sidx = v ? g_sidx[e * T_TOT + slot] : 0;
        s_sidx[tid] = sidx;
        s_tok[tid]  = v ? (sidx >> 1) : 0;
        s_gate[tid] = v ? g_gate[e * T_TOT + slot] : 0.f;
    }
    __syncthreads();

    // A loader: 2 threads per row (64B halves); B loader: 1 thread per row (256 rows)
    int row = tid >> 1, hf = tid & 1;
    size_t arow = (size_t)s_tok[row] * DD + hf * 32;
    const __half* bsrc = g_w1 + ((size_t)(e * 2 + nt) * 256 + tid) * 1024;
    uint32_t swoA[4], swoB[8];
#pragma unroll
    for (int i = 0; i < 4; i++) swoA[i] = sw_off(row, hf * 4 + i);
#pragma unroll
    for (int i = 0; i < 8; i++) swoB[i] = sw_off(tid, i);

    auto loadStage = [&](int kc, int s) {
        uint32_t dst = smb + s * STAGE;
        const __half* ah = g_xh + arow + kc * 64;
        const __half* al = g_xl + arow + kc * 64;
        const __half* bb = bsrc + kc * 64;
#pragma unroll
        for (int i = 0; i < 4; i++) {
            cp16(dst + swoA[i],         ah + i * 8);
            cp16(dst + TILEA + swoA[i], al + i * 8);
        }
#pragma unroll
        for (int i = 0; i < 8; i++) cp16(dst + BOFF + swoB[i], bb + i * 8);
    };

    MmaCore mc;
    mma_core_init(mc, wid, lane);
    int wm = wid & 1, wn = wid >> 1;

    float c[4][8][4];
#pragma unroll
    for (int i = 0; i < 4; i++)
#pragma unroll
        for (int j = 0; j < 8; j++)
#pragma unroll
            for (int q = 0; q < 4; q++) c[i][j][q] = 0.f;

    const int NIT = DD / 64;   // 16
    loadStage(0, 0); CP_COMMIT();
    for (int it = 0; it < NIT; ++it) {
        int s = it & 1;
        if (it + 1 < NIT) { loadStage(it + 1, s ^ 1); CP_COMMIT(); CP_WAIT1(); }
        else              { CP_WAIT0(); }
        __syncthreads();
        mma_chunk(mc, smb + s * STAGE, c);
        __syncthreads();
    }

    // epilogue: stage C (128x256 fp32), fuse s = gate*silu(u)*v, store fp16 hi/lo
    float* smC = (float*)sm;
#pragma unroll
    for (int im = 0; im < 4; im++) {
        int r1 = wm * 64 + im * 16 + (lane >> 2);
#pragma unroll
        for (int jn = 0; jn < 8; jn++) {
            int cb = wn * 64 + jn * 8 + ((lane & 3) << 1);
            *(float2*)&smC[r1 * CPAD + cb]       = make_float2(c[im][jn][0], c[im][jn][1]);
            *(float2*)&smC[(r1 + 8) * CPAD + cb] = make_float2(c[im][jn][2], c[im][jn][3]);
        }
    }
    __syncthreads();

    int rr = tid >> 1, seg = tid & 1;
    int slot = mbase + rr;
    if (slot < cnt) {
        int sidx = s_sidx[rr];
        float gate = s_gate[rr];
        size_t ob = (size_t)sidx * RR + nt * 128 + seg * 64;
        const float* uptr = &smC[rr * CPAD + seg * 64];
        const float* vptr = uptr + 128;
#pragma unroll
        for (int j = 0; j < 64; j += 2) {
            float u0 = uptr[j], u1 = uptr[j + 1];
            float v0 = vptr[j], v1 = vptr[j + 1];
            float s0 = gate * u0 * v0 / (1.f + __expf(-u0));
            float s1 = gate * u1 * v1 / (1.f + __expf(-u1));
            __half h2[2], l2[2];
            split_f16(s0, h2[0], l2[0]);
            split_f16(s1, h2[1], l2[1]);
            *(uint32_t*)(g_sh + ob + j) = *(const uint32_t*)h2;
            *(uint32_t*)(g_sl + ob + j) = *(const uint32_t*)l2;
        }
    }
}

// ==================== pass2: slots x (R hi/lo) * Wo -> g_Y ====================
__global__ __launch_bounds__(256, 1)
void pass2_mma() {
    int e = blockIdx.z;
    int ntile = blockIdx.y;              // d-base = ntile*256
    int cnt = g_count[e];
    int mbase = blockIdx.x * 128;
    if (mbase >= cnt) return;

    extern __shared__ char sm[];
    uint32_t smb = smem_u32(sm);
    __shared__ int s_row[128];
    __shared__ int s_val[128];

    int tid = threadIdx.x, lane = tid & 31, wid = tid >> 5;

    if (tid < 128) {
        int slot = mbase + tid;
        bool v = slot < cnt;
        s_row[tid] = v ? g_sidx[e * T_TOT + slot] : 0;
        s_val[tid] = v ? 1 : 0;
    }
    __syncthreads();

    int row = tid >> 1, hf = tid & 1;
    size_t arow = (size_t)s_row[row] * RR + hf * 32;
    const __half* bsrc = g_wop + ((size_t)e * DD + ntile * 256 + tid) * 256;
    uint32_t swoA[4], swoB[8];
#pragma unroll
    for (int i = 0; i < 4; i++) swoA[i] = sw_off(row, hf * 4 + i);
#pragma unroll
    for (int i = 0; i < 8; i++) swoB[i] = sw_off(tid, i);

    auto loadStage = [&](int kc, int s) {
        uint32_t dst = smb + s * STAGE;
        const __half* ah = g_sh + arow + kc * 64;
        const __half* al = g_sl + arow + kc * 64;
        const __half* bb = bsrc + kc * 64;
#pragma unroll
        for (int i = 0; i < 4; i++) {
            cp16(dst + swoA[i],         ah + i * 8);
            cp16(dst + TILEA + swoA[i], al + i * 8);
        }
#pragma unroll
        for (int i = 0; i < 8; i++) cp16(dst + BOFF + swoB[i], bb + i * 8);
    };

    MmaCore mc;
    mma_core_init(mc, wid, lane);
    int wm = wid & 1, wn = wid >> 1;

    float c[4][8][4];
#pragma unroll
    for (int i = 0; i < 4; i++)
#pragma unroll
        for (int j = 0; j < 8; j++)
#pragma unroll
            for (int q = 0; q < 4; q++) c[i][j][q] = 0.f;

    const int NIT = RR / 64;   // 4
    loadStage(0, 0); CP_COMMIT();
    for (int it = 0; it < NIT; ++it) {
        int s = it & 1;
        if (it + 1 < NIT) { loadStage(it + 1, s ^ 1); CP_COMMIT(); CP_WAIT1(); }
        else              { CP_WAIT0(); }
        __syncthreads();
        mma_chunk(mc, smb + s * STAGE, c);
        __syncthreads();
    }

    // epilogue: plain float2 stores into per-slot Y rows
#pragma unroll
    for (int im = 0; im < 4; im++) {
        int rl = wm * 64 + im * 16 + (lane >> 2);
        int ok0 = s_val[rl], ok1 = s_val[rl + 8];
        int r0 = s_row[rl],  r1 = s_row[rl + 8];
#pragma unroll
        for (int jn = 0; jn < 8; jn++) {
            int col = ntile * 256 + wn * 64 + jn * 8 + ((lane & 3) << 1);
            if (ok0) *(float2*)(g_Y + (size_t)r0 * DD + col) = make_float2(c[im][jn][0], c[im][jn][1]);
            if (ok1) *(float2*)(g_Y + (size_t)r1 * DD + col) = make_float2(c[im][jn][2], c[im][jn][3]);
        }
    }
}

// -------- combine: out[t] = Y[2t] + Y[2t+1] --------
__global__ void combine_kernel(float4* __restrict__ out4) {
    const int D4 = DD / 4;
    int n = T_TOT * D4;
    int stride = gridDim.x * blockDim.x;
    const float4* Y4 = (const float4*)g_Y;
    for (int i = blockIdx.x * blockDim.x + threadIdx.x; i < n; i += stride) {
        int t = i / D4, d4 = i - t * D4;
        float4 a = Y4[(size_t)(2 * t) * D4 + d4];
        float4 b = Y4[(size_t)(2 * t + 1) * D4 + d4];
        out4[i] = make_float4(a.x + b.x, a.y + b.y, a.z + b.z, a.w + b.w);
    }
}

// -------- launch (pass1_mma deliberately at launch slot #4 for ncu capture) --------
extern "C" void kernel_launch(void* const* d_in, const int* in_sizes, int n_in,
                              void* d_out, int out_size) {
    (void)in_sizes; (void)n_in; (void)out_size;
    const float* x  = (const float*)d_in[0];
    const float* gw = (const float*)d_in[1];
    const float* Wu = (const float*)d_in[2];
    const float* Wv = (const float*)d_in[3];
    const float* Wo = (const float*)d_in[4];
    float* out = (float*)d_out;

    cudaFuncSetAttribute(pass1_mma, cudaFuncAttributeMaxDynamicSharedMemorySize, MMA_DSMEM);
    cudaFuncSetAttribute(pass2_mma, cudaFuncAttributeMaxDynamicSharedMemorySize, MMA_DSMEM);

    init_kernel<<<1, 32>>>();                                       // 1
    router_split_kernel<<<T_TOT / 8, 256>>>(x, gw);                 // 2
    pack_w1_kernel<<<dim3(DD / 32, RR / 32, EE * 2), 256>>>(Wu, Wv);// 3

    dim3 g1(64, 2, EE);    // M-tiles x r-halves x experts (early-exit on count)
    pass1_mma<<<g1, 256, MMA_DSMEM>>>();                            // 4  <- profiled

    pack_wo_kernel<<<dim3(DD / 32, RR / 32, EE), 256>>>(Wo);        // 5

    dim3 g2(64, 4, EE);    // M-tiles x d-tiles(256) x experts
    pass2_mma<<<g2, 256, MMA_DSMEM>>>();                            // 6

    combine_kernel<<<1024, 256>>>((float4*)out);                    // 7
}

// round 10
// speedup vs baseline: 2.1381x; 1.0785x over previous
#include <cuda_runtime.h>
#include <cuda_fp16.h>
#include <math.h>
#include <stdint.h>

// Problem constants
#define T_TOT 8192   // B*N tokens
#define DD    1024
#define EE    8
#define RR    256
#define NSLOT (T_TOT * 2)

// -------- scratch (__device__ globals; no allocations allowed) --------
__device__ int   g_count[EE];
__device__ int   g_sidx[EE * T_TOT];          // sidx = token*2 + k
__device__ float g_gate[EE * T_TOT];
__device__ __half g_xh[T_TOT * DD];           // x hi/lo split (fp16)
__device__ __half g_xl[T_TOT * DD];
__device__ __half g_sh[NSLOT * RR];           // s = gate*silu(u)*v hi/lo
__device__ __half g_sl[NSLOT * RR];
__device__ float g_Y[NSLOT * DD];             // per-slot down-proj output (64 MB)
// pass1 B packed (fp16): [e][nt(4)][n(128)][k(1024)]
//   n<64: Wu row 64*nt+n ; n>=64: Wv row 64*nt + (n-64)
__device__ __half g_w1[EE * 4 * 128 * 1024];
// pass2 B packed (fp16): [e][d(1024)][k(256)]
__device__ __half g_wop[EE * DD * 256];

// -------- PTX helpers (base sm_103 features only) --------
__device__ __forceinline__ uint32_t smem_u32(const void* p) {
    uint32_t a;
    asm("{ .reg .u64 t; cvta.to.shared.u64 t, %1; cvt.u32.u64 %0, t; }" : "=r"(a) : "l"(p));
    return a;
}
__device__ __forceinline__ void cp16(uint32_t dst, const void* src) {
    asm volatile("cp.async.cg.shared.global [%0], [%1], 16;" :: "r"(dst), "l"(src));
}
#define CP_COMMIT() asm volatile("cp.async.commit_group;" ::: "memory")
#define CP_WAIT1()  asm volatile("cp.async.wait_group 1;" ::: "memory")
#define CP_WAIT0()  asm volatile("cp.async.wait_group 0;" ::: "memory")

__device__ __forceinline__ void ldsm_x4(uint32_t r[4], uint32_t addr) {
    asm volatile("ldmatrix.sync.aligned.m8n8.x4.shared.b16 {%0,%1,%2,%3}, [%4];"
                 : "=r"(r[0]), "=r"(r[1]), "=r"(r[2]), "=r"(r[3]) : "r"(addr));
}
__device__ __forceinline__ void mma_f16(float c[4],
                                        const uint32_t a[4],
                                        uint32_t b0, uint32_t b1) {
    asm("mma.sync.aligned.m16n8k16.row.col.f32.f16.f16.f32 "
        "{%0,%1,%2,%3}, {%4,%5,%6,%7}, {%8,%9}, {%0,%1,%2,%3};"
        : "+f"(c[0]), "+f"(c[1]), "+f"(c[2]), "+f"(c[3])
        : "r"(a[0]), "r"(a[1]), "r"(a[2]), "r"(a[3]), "r"(b0), "r"(b1));
}
// SW128 swizzle for 128B rows: byte offset for (row, 16B-group g)
__device__ __forceinline__ uint32_t sw_off(int row, int g) {
    return (uint32_t)row * 128u + (uint32_t)((g ^ (row & 7)) << 4);
}
__device__ __forceinline__ void split_f16(float v, __half& h, __half& l) {
    h = __float2half_rn(v);
    l = __float2half_rn(v - __half2float(h));
}

// -------- init: zero counters --------
__global__ void init_kernel() {
    if (threadIdx.x < EE) g_count[threadIdx.x] = 0;
}

// -------- router + x split (fused) --------
__global__ void router_split_kernel(const float* __restrict__ x,
                                    const float* __restrict__ gw) {
    int warp = (blockIdx.x * blockDim.x + threadIdx.x) >> 5;
    int lane = threadIdx.x & 31;
    {
        const float* xr = x + (size_t)warp * DD;
        float acc[EE];
#pragma unroll
        for (int e = 0; e < EE; e++) acc[e] = 0.f;
        for (int d = lane * 4; d < DD; d += 32 * 4) {
            float4 xv = *(const float4*)(xr + d);
            const float* xp = (const float*)&xv;
#pragma unroll
            for (int j = 0; j < 4; j++) {
                float xs = xp[j];
                float4 g0 = *(const float4*)(gw + (size_t)(d + j) * EE);
                float4 g1 = *(const float4*)(gw + (size_t)(d + j) * EE + 4);
                acc[0] += xs * g0.x; acc[1] += xs * g0.y;
                acc[2] += xs * g0.z; acc[3] += xs * g0.w;
                acc[4] += xs * g1.x; acc[5] += xs * g1.y;
                acc[6] += xs * g1.z; acc[7] += xs * g1.w;
            }
        }
#pragma unroll
        for (int e = 0; e < EE; e++)
#pragma unroll
            for (int off = 16; off; off >>= 1)
                acc[e] += __shfl_xor_sync(0xFFFFFFFFu, acc[e], off);

        if (lane == 0) {
            int i0 = 0; float v0 = acc[0];
#pragma unroll
            for (int e = 1; e < EE; e++) if (acc[e] > v0) { v0 = acc[e]; i0 = e; }
            int i1 = -1; float v1 = -INFINITY;
#pragma unroll
            for (int e = 0; e < EE; e++) if (e != i0 && acc[e] > v1) { v1 = acc[e]; i1 = e; }
            float w0 = 1.f / (1.f + expf(v1 - v0));
            float w1 = 1.f - w0;
            int p0 = atomicAdd(&g_count[i0], 1);
            g_sidx[i0 * T_TOT + p0] = warp * 2 + 0;
            g_gate[i0 * T_TOT + p0] = w0;
            int p1 = atomicAdd(&g_count[i1], 1);
            g_sidx[i1 * T_TOT + p1] = warp * 2 + 1;
            g_gate[i1 * T_TOT + p1] = w1;
        }
    }
    // ---- x hi/lo split (grid-stride over float4) ----
    const float4* x4 = (const float4*)x;
    int n4 = T_TOT * DD / 4;
    int stride = gridDim.x * blockDim.x;
    for (int i = blockIdx.x * blockDim.x + threadIdx.x; i < n4; i += stride) {
        float4 v = x4[i];
        const float* vp = (const float*)&v;
        __half h[4], l[4];
#pragma unroll
        for (int j = 0; j < 4; j++) split_f16(vp[j], h[j], l[j]);
        *(uint2*)(g_xh + (size_t)i * 4) = *(const uint2*)h;
        *(uint2*)(g_xl + (size_t)i * 4) = *(const uint2*)l;
    }
}

// -------- prep: pack Wu/Wv -> g_w1 (transpose [d][r] -> [n][k=d], fp16) --------
__global__ void pack_w1_kernel(const float* __restrict__ Wu,
                               const float* __restrict__ Wv) {
    int e = blockIdx.z & 7;
    int isV = blockIdx.z >> 3;
    const float* W = (isV ? Wv : Wu) + (size_t)e * DD * RR;

    __shared__ float tile[32][33];
    int d0 = blockIdx.x * 32, r0 = blockIdx.y * 32;
    int tid = threadIdx.x;

    int dl = tid >> 3, rl = (tid & 7) * 4;
    float4 v = *(const float4*)(W + (size_t)(d0 + dl) * RR + r0 + rl);
    tile[dl][rl + 0] = v.x; tile[dl][rl + 1] = v.y;
    tile[dl][rl + 2] = v.z; tile[dl][rl + 3] = v.w;
    __syncthreads();

    int dp = (tid & 15) * 2;
#pragma unroll
    for (int rr = tid >> 4; rr < 32; rr += 16) {
        __half p2[2];
        p2[0] = __float2half_rn(tile[dp][rr]);
        p2[1] = __float2half_rn(tile[dp + 1][rr]);
        int r = r0 + rr;
        int nt = r >> 6;
        int n = (r & 63) + isV * 64;
        size_t base = ((size_t)(e * 4 + nt) * 128 + n) * 1024 + d0 + dp;
        *(uint32_t*)(g_w1 + base) = *(const uint32_t*)p2;
    }
}

// -------- prep: pack Wo[e][r][d] -> g_wop[e][d][k=r] (fp16) --------
__global__ void pack_wo_kernel(const float* __restrict__ Wo) {
    int e = blockIdx.z;
    const float* W = Wo + (size_t)e * RR * DD;   // [r][d]

    __shared__ float tile[32][33];               // tile[r][d]
    int d0 = blockIdx.x * 32, r0 = blockIdx.y * 32;
    int tid = threadIdx.x;

    int rl = tid >> 3, dl = (tid & 7) * 4;
    float4 v = *(const float4*)(W + (size_t)(r0 + rl) * DD + d0 + dl);
    tile[rl][dl + 0] = v.x; tile[rl][dl + 1] = v.y;
    tile[rl][dl + 2] = v.z; tile[rl][dl + 3] = v.w;
    __syncthreads();

    int rp = (tid & 15) * 2;
#pragma unroll
    for (int dd = tid >> 4; dd < 32; dd += 16) {
        __half p2[2];
        p2[0] = __float2half_rn(tile[rp][dd]);
        p2[1] = __float2half_rn(tile[rp + 1][dd]);
        size_t base = ((size_t)e * DD + d0 + dd) * 256 + r0 + rp;
        *(uint32_t*)(g_wop + base) = *(const uint32_t*)p2;
    }
}

// ==================== 2-term fp16 MMA core (2 CTAs/SM) ====================
// Stage (48 KB): [Ah 16K][Al 16K][B 16K]; 2 stages = 96 KB.
// BM=128, BN=128, BK=64. 8 warps as 2(m) x 4(n); warptile 64m x 32n.
// C += Ah*B + Al*B   (A = Ah + Al exactly; B rounded once to fp16)
#define TILEA  16384
#define BOFF   32768
#define STAGE  49152
#define CPAD   132
#define MMA_DSMEM (2 * STAGE)   // 98304; epilogue 128*132*4 = 67584 fits

struct MmaCore {
    uint32_t rowA[4];
    uint32_t rowB[2];
    int koct, rx;
};
__device__ __forceinline__ void mma_core_init(MmaCore& mc, int wid, int lane) {
    int wm = wid & 1, wn = wid >> 1;
    int rloc = lane & 15;
    mc.koct = lane >> 4;
    mc.rx = rloc & 7;
#pragma unroll
    for (int im = 0; im < 4; im++) mc.rowA[im] = (uint32_t)(wm * 64 + im * 16 + rloc) * 128u;
#pragma unroll
    for (int h = 0; h < 2; h++) mc.rowB[h] = (uint32_t)(wn * 32 + h * 16 + rloc) * 128u;
}
__device__ __forceinline__ void mma_chunk(const MmaCore& mc, uint32_t sb, float c[4][4][4]) {
#pragma unroll
    for (int ks = 0; ks < 4; ks++) {
        uint32_t kx = (uint32_t)(((2 * ks + mc.koct) ^ mc.rx) << 4);
        uint32_t ah[4][4], al[4][4];
#pragma unroll
        for (int im = 0; im < 4; im++) {
            ldsm_x4(ah[im], sb + mc.rowA[im] + kx);
            ldsm_x4(al[im], sb + TILEA + mc.rowA[im] + kx);
        }
#pragma unroll
        for (int h = 0; h < 2; h++) {
            uint32_t b[4];
            ldsm_x4(b, sb + BOFF + mc.rowB[h] + kx);
#pragma unroll
            for (int im = 0; im < 4; im++) {
                mma_f16(c[im][2 * h],     ah[im], b[0], b[2]);
                mma_f16(c[im][2 * h + 1], ah[im], b[1], b[3]);
            }
#pragma unroll
            for (int im = 0; im < 4; im++) {
                mma_f16(c[im][2 * h],     al[im], b[0], b[2]);
                mma_f16(c[im][2 * h + 1], al[im], b[1], b[3]);
            }
        }
    }
}

// ==================== pass1: slots x (D hi/lo) * W1 -> U|V, fuse SwiGLU ====================
__global__ __launch_bounds__(256, 2)
void pass1_mma() {
    int e = blockIdx.z;
    int nt = blockIdx.y;                 // cols 0..63 = U rows 64nt.., 64..127 = V
    int cnt = g_count[e];
    int mbase = blockIdx.x * 128;
    if (mbase >= cnt) return;

    extern __shared__ char sm[];
    uint32_t smb = smem_u32(sm);
    __shared__ int   s_sidx[128];
    __shared__ int   s_tok[128];
    __shared__ float s_gate[128];

    int tid = threadIdx.x, lane = tid & 31, wid = tid >> 5;

    if (tid < 128) {
        int slot = mbase + tid;
        bool v = slot < cnt;
        int sidx = v ? g_sidx[e * T_TOT + slot] : 0;
        s_sidx[tid] = sidx;
        s_tok[tid]  = v ? (sidx >> 1) : 0;
        s_gate[tid] = v ? g_gate[e * T_TOT + slot] : 0.f;
    }
    __syncthreads();

    // loaders: A and B tiles are both 128 rows x 128B; 2 threads per row
    int row = tid >> 1, hf = tid & 1;
    size_t arow = (size_t)s_tok[row] * DD + hf * 32;
    const __half* bsrc = g_w1 + ((size_t)(e * 4 + nt) * 128 + row) * 1024 + hf * 32;
    uint32_t swo[4];
#pragma unroll
    for (int i = 0; i < 4; i++) swo[i] = sw_off(row, hf * 4 + i);

    auto loadStage = [&](int kc, int s) {
        uint32_t dst = smb + s * STAGE;
        const __half* ah = g_xh + arow + kc * 64;
        const __half* al = g_xl + arow + kc * 64;
        const __half* bb = bsrc + kc * 64;
#pragma unroll
        for (int i = 0; i < 4; i++) {
            cp16(dst + swo[i],         ah + i * 8);
            cp16(dst + TILEA + swo[i], al + i * 8);
            cp16(dst + BOFF + swo[i],  bb + i * 8);
        }
    };

    MmaCore mc;
    mma_core_init(mc, wid, lane);
    int wm = wid & 1, wn = wid >> 1;

    float c[4][4][4];
#pragma unroll
    for (int i = 0; i < 4; i++)
#pragma unroll
        for (int j = 0; j < 4; j++)
#pragma unroll
            for (int q = 0; q < 4; q++) c[i][j][q] = 0.f;

    const int NIT = DD / 64;   // 16
    loadStage(0, 0); CP_COMMIT();
    for (int it = 0; it < NIT; ++it) {
        int s = it & 1;
        if (it + 1 < NIT) { loadStage(it + 1, s ^ 1); CP_COMMIT(); CP_WAIT1(); }
        else              { CP_WAIT0(); }
        __syncthreads();
        mma_chunk(mc, smb + s * STAGE, c);
        __syncthreads();
    }

    // epilogue: stage C (128x128 fp32), fuse s = gate*silu(u)*v, store fp16 hi/lo
    float* smC = (float*)sm;
#pragma unroll
    for (int im = 0; im < 4; im++) {
        int r1 = wm * 64 + im * 16 + (lane >> 2);
#pragma unroll
        for (int jn = 0; jn < 4; jn++) {
            int cb = wn * 32 + jn * 8 + ((lane & 3) << 1);
            *(float2*)&smC[r1 * CPAD + cb]       = make_float2(c[im][jn][0], c[im][jn][1]);
            *(float2*)&smC[(r1 + 8) * CPAD + cb] = make_float2(c[im][jn][2], c[im][jn][3]);
        }
    }
    __syncthreads();

    int rr = tid >> 1, seg = tid & 1;
    int slot = mbase + rr;
    if (slot < cnt) {
        int sidx = s_sidx[rr];
        float gate = s_gate[rr];
        size_t ob = (size_t)sidx * RR + nt * 64 + seg * 32;
        const float* uptr = &smC[rr * CPAD + seg * 32];
        const float* vptr = uptr + 64;
#pragma unroll
        for (int j = 0; j < 32; j += 2) {
            float u0 = uptr[j], u1 = uptr[j + 1];
            float v0 = vptr[j], v1 = vptr[j + 1];
            float s0 = gate * u0 * v0 / (1.f + __expf(-u0));
            float s1 = gate * u1 * v1 / (1.f + __expf(-u1));
            __half h2[2], l2[2];
            split_f16(s0, h2[0], l2[0]);
            split_f16(s1, h2[1], l2[1]);
            *(uint32_t*)(g_sh + ob + j) = *(const uint32_t*)h2;
            *(uint32_t*)(g_sl + ob + j) = *(const uint32_t*)l2;
        }
    }
}

// ==================== pass2: slots x (R hi/lo) * Wo -> g_Y ====================
__global__ __launch_bounds__(256, 2)
void pass2_mma() {
    int e = blockIdx.z;
    int ntile = blockIdx.y;              // d-base = ntile*128
    int cnt = g_count[e];
    int mbase = blockIdx.x * 128;
    if (mbase >= cnt) return;

    extern __shared__ char sm[];
    uint32_t smb = smem_u32(sm);
    __shared__ int s_row[128];
    __shared__ int s_val[128];

    int tid = threadIdx.x, lane = tid & 31, wid = tid >> 5;

    if (tid < 128) {
        int slot = mbase + tid;
        bool v = slot < cnt;
        s_row[tid] = v ? g_sidx[e * T_TOT + slot] : 0;
        s_val[tid] = v ? 1 : 0;
    }
    __syncthreads();

    int row = tid >> 1, hf = tid & 1;
    size_t arow = (size_t)s_row[row] * RR + hf * 32;
    const __half* bsrc = g_wop + ((size_t)e * DD + ntile * 128 + row) * 256 + hf * 32;
    uint32_t swo[4];
#pragma unroll
    for (int i = 0; i < 4; i++) swo[i] = sw_off(row, hf * 4 + i);

    auto loadStage = [&](int kc, int s) {
        uint32_t dst = smb + s * STAGE;
        const __half* ah = g_sh + arow + kc * 64;
        const __half* al = g_sl + arow + kc * 64;
        const __half* bb = bsrc + kc * 64;
#pragma unroll
        for (int i = 0; i < 4; i++) {
            cp16(dst + swo[i],         ah + i * 8);
            cp16(dst + TILEA + swo[i], al + i * 8);
            cp16(dst + BOFF + swo[i],  bb + i * 8);
        }
    };

    MmaCore mc;
    mma_core_init(mc, wid, lane);
    int wm = wid & 1, wn = wid >> 1;

    float c[4][4][4];
#pragma unroll
    for (int i = 0; i < 4; i++)
#pragma unroll
        for (int j = 0; j < 4; j++)
#pragma unroll
            for (int q = 0; q < 4; q++) c[i][j][q] = 0.f;

    const int NIT = RR / 64;   // 4
    loadStage(0, 0); CP_COMMIT();
    for (int it = 0; it < NIT; ++it) {
        int s = it & 1;
        if (it + 1 < NIT) { loadStage(it + 1, s ^ 1); CP_COMMIT(); CP_WAIT1(); }
        else              { CP_WAIT0(); }
        __syncthreads();
        mma_chunk(mc, smb + s * STAGE, c);
        __syncthreads();
    }

    // epilogue: plain float2 stores into per-slot Y rows
#pragma unroll
    for (int im = 0; im < 4; im++) {
        int rl = wm * 64 + im * 16 + (lane >> 2);
        int ok0 = s_val[rl], ok1 = s_val[rl + 8];
        int r0 = s_row[rl],  r1 = s_row[rl + 8];
#pragma unroll
        for (int jn = 0; jn < 4; jn++) {
            int col = ntile * 128 + wn * 32 + jn * 8 + ((lane & 3) << 1);
            if (ok0) *(float2*)(g_Y + (size_t)r0 * DD + col) = make_float2(c[im][jn][0], c[im][jn][1]);
            if (ok1) *(float2*)(g_Y + (size_t)r1 * DD + col) = make_float2(c[im][jn][2], c[im][jn][3]);
        }
    }
}

// -------- combine: out[t] = Y[2t] + Y[2t+1] --------
__global__ void combine_kernel(float4* __restrict__ out4) {
    const int D4 = DD / 4;
    int n = T_TOT * D4;
    int stride = gridDim.x * blockDim.x;
    const float4* Y4 = (const float4*)g_Y;
    for (int i = blockIdx.x * blockDim.x + threadIdx.x; i < n; i += stride) {
        int t = i / D4, d4 = i - t * D4;
        float4 a = Y4[(size_t)(2 * t) * D4 + d4];
        float4 b = Y4[(size_t)(2 * t + 1) * D4 + d4];
        out4[i] = make_float4(a.x + b.x, a.y + b.y, a.z + b.z, a.w + b.w);
    }
}

// -------- launch (pass1_mma at launch slot #4 for ncu capture) --------
extern "C" void kernel_launch(void* const* d_in, const int* in_sizes, int n_in,
                              void* d_out, int out_size) {
    (void)in_sizes; (void)n_in; (void)out_size;
    const float* x  = (const float*)d_in[0];
    const float* gw = (const float*)d_in[1];
    const float* Wu = (const float*)d_in[2];
    const float* Wv = (const float*)d_in[3];
    const float* Wo = (const float*)d_in[4];
    float* out = (float*)d_out;

    cudaFuncSetAttribute(pass1_mma, cudaFuncAttributeMaxDynamicSharedMemorySize, MMA_DSMEM);
    cudaFuncSetAttribute(pass2_mma, cudaFuncAttributeMaxDynamicSharedMemorySize, MMA_DSMEM);

    init_kernel<<<1, 32>>>();                                       // 1
    router_split_kernel<<<T_TOT / 8, 256>>>(x, gw);                 // 2
    pack_w1_kernel<<<dim3(DD / 32, RR / 32, EE * 2), 256>>>(Wu, Wv);// 3

    dim3 g1(64, 4, EE);    // M-tiles x r-tiles(64) x experts (early-exit on count)
    pass1_mma<<<g1, 256, MMA_DSMEM>>>();                            // 4  <- profiled

    pack_wo_kernel<<<dim3(DD / 32, RR / 32, EE), 256>>>(Wo);        // 5

    dim3 g2(64, 8, EE);    // M-tiles x d-tiles(128) x experts
    pass2_mma<<<g2, 256, MMA_DSMEM>>>();                            // 6

    combine_kernel<<<1024, 256>>>((float4*)out);                    // 7
}

// round 11
// speedup vs baseline: 2.9893x; 1.3981x over previous
#include <cuda_runtime.h>
#include <cuda_fp16.h>
#include <math.h>
#include <stdint.h>

// Problem constants
#define T_TOT 8192   // B*N tokens
#define DD    1024
#define EE    8
#define RR    256
#define NSLOT (T_TOT * 2)

// -------- scratch (__device__ globals; no allocations allowed) --------
__device__ int   g_count[EE];
__device__ int   g_sidx[EE * T_TOT];          // sidx = token*2 + k
__device__ float g_gate[EE * T_TOT];
__device__ __half g_x16[T_TOT * DD];          // x rounded to fp16
__device__ __half g_s16[NSLOT * RR];          // s = gate*silu(u)*v, fp16
__device__ float g_Y[NSLOT * DD];             // per-slot down-proj output (64 MB)
// pass1 B packed (fp16): [e][nt(4)][n(128)][k(1024)]
//   n<64: Wu row 64*nt+n ; n>=64: Wv row 64*nt + (n-64)
__device__ __half g_w1[EE * 4 * 128 * 1024];
// pass2 B packed (fp16): [e][d(1024)][k(256)]
__device__ __half g_wop[EE * DD * 256];

// -------- PTX helpers (base sm_103 features only) --------
__device__ __forceinline__ uint32_t smem_u32(const void* p) {
    uint32_t a;
    asm("{ .reg .u64 t; cvta.to.shared.u64 t, %1; cvt.u32.u64 %0, t; }" : "=r"(a) : "l"(p));
    return a;
}
__device__ __forceinline__ void cp16(uint32_t dst, const void* src) {
    asm volatile("cp.async.cg.shared.global [%0], [%1], 16;" :: "r"(dst), "l"(src));
}
#define CP_COMMIT() asm volatile("cp.async.commit_group;" ::: "memory")
#define CP_WAIT1()  asm volatile("cp.async.wait_group 1;" ::: "memory")
#define CP_WAIT0()  asm volatile("cp.async.wait_group 0;" ::: "memory")

__device__ __forceinline__ void ldsm_x4(uint32_t r[4], uint32_t addr) {
    asm volatile("ldmatrix.sync.aligned.m8n8.x4.shared.b16 {%0,%1,%2,%3}, [%4];"
                 : "=r"(r[0]), "=r"(r[1]), "=r"(r[2]), "=r"(r[3]) : "r"(addr));
}
__device__ __forceinline__ void mma_f16(float c[4],
                                        const uint32_t a[4],
                                        uint32_t b0, uint32_t b1) {
    asm("mma.sync.aligned.m16n8k16.row.col.f32.f16.f16.f32 "
        "{%0,%1,%2,%3}, {%4,%5,%6,%7}, {%8,%9}, {%0,%1,%2,%3};"
        : "+f"(c[0]), "+f"(c[1]), "+f"(c[2]), "+f"(c[3])
        : "r"(a[0]), "r"(a[1]), "r"(a[2]), "r"(a[3]), "r"(b0), "r"(b1));
}
// SW128 swizzle for 128B rows: byte offset for (row, 16B-group g)
__device__ __forceinline__ uint32_t sw_off(int row, int g) {
    return (uint32_t)row * 128u + (uint32_t)((g ^ (row & 7)) << 4);
}

// -------- init: zero counters --------
__global__ void init_kernel() {
    if (threadIdx.x < EE) g_count[threadIdx.x] = 0;
}

// -------- router + x->fp16 convert (fused) --------
__global__ void router_split_kernel(const float* __restrict__ x,
                                    const float* __restrict__ gw) {
    int warp = (blockIdx.x * blockDim.x + threadIdx.x) >> 5;
    int lane = threadIdx.x & 31;
    {
        const float* xr = x + (size_t)warp * DD;
        float acc[EE];
#pragma unroll
        for (int e = 0; e < EE; e++) acc[e] = 0.f;
        for (int d = lane * 4; d < DD; d += 32 * 4) {
            float4 xv = *(const float4*)(xr + d);
            const float* xp = (const float*)&xv;
#pragma unroll
            for (int j = 0; j < 4; j++) {
                float xs = xp[j];
                float4 g0 = *(const float4*)(gw + (size_t)(d + j) * EE);
                float4 g1 = *(const float4*)(gw + (size_t)(d + j) * EE + 4);
                acc[0] += xs * g0.x; acc[1] += xs * g0.y;
                acc[2] += xs * g0.z; acc[3] += xs * g0.w;
                acc[4] += xs * g1.x; acc[5] += xs * g1.y;
                acc[6] += xs * g1.z; acc[7] += xs * g1.w;
            }
        }
#pragma unroll
        for (int e = 0; e < EE; e++)
#pragma unroll
            for (int off = 16; off; off >>= 1)
                acc[e] += __shfl_xor_sync(0xFFFFFFFFu, acc[e], off);

        if (lane == 0) {
            int i0 = 0; float v0 = acc[0];
#pragma unroll
            for (int e = 1; e < EE; e++) if (acc[e] > v0) { v0 = acc[e]; i0 = e; }
            int i1 = -1; float v1 = -INFINITY;
#pragma unroll
            for (int e = 0; e < EE; e++) if (e != i0 && acc[e] > v1) { v1 = acc[e]; i1 = e; }
            float w0 = 1.f / (1.f + expf(v1 - v0));
            float w1 = 1.f - w0;
            int p0 = atomicAdd(&g_count[i0], 1);
            g_sidx[i0 * T_TOT + p0] = warp * 2 + 0;
            g_gate[i0 * T_TOT + p0] = w0;
            int p1 = atomicAdd(&g_count[i1], 1);
            g_sidx[i1 * T_TOT + p1] = warp * 2 + 1;
            g_gate[i1 * T_TOT + p1] = w1;
        }
    }
    // ---- x -> fp16 (grid-stride over float4) ----
    const float4* x4 = (const float4*)x;
    int n4 = T_TOT * DD / 4;
    int stride = gridDim.x * blockDim.x;
    for (int i = blockIdx.x * blockDim.x + threadIdx.x; i < n4; i += stride) {
        float4 v = x4[i];
        __half h[4];
        h[0] = __float2half_rn(v.x); h[1] = __float2half_rn(v.y);
        h[2] = __float2half_rn(v.z); h[3] = __float2half_rn(v.w);
        *(uint2*)(g_x16 + (size_t)i * 4) = *(const uint2*)h;
    }
}

// -------- prep: pack Wu/Wv -> g_w1 (transpose [d][r] -> [n][k=d], fp16) --------
__global__ void pack_w1_kernel(const float* __restrict__ Wu,
                               const float* __restrict__ Wv) {
    int e = blockIdx.z & 7;
    int isV = blockIdx.z >> 3;
    const float* W = (isV ? Wv : Wu) + (size_t)e * DD * RR;

    __shared__ float tile[32][33];
    int d0 = blockIdx.x * 32, r0 = blockIdx.y * 32;
    int tid = threadIdx.x;

    int dl = tid >> 3, rl = (tid & 7) * 4;
    float4 v = *(const float4*)(W + (size_t)(d0 + dl) * RR + r0 + rl);
    tile[dl][rl + 0] = v.x; tile[dl][rl + 1] = v.y;
    tile[dl][rl + 2] = v.z; tile[dl][rl + 3] = v.w;
    __syncthreads();

    int dp = (tid & 15) * 2;
#pragma unroll
    for (int rr = tid >> 4; rr < 32; rr += 16) {
        __half p2[2];
        p2[0] = __float2half_rn(tile[dp][rr]);
        p2[1] = __float2half_rn(tile[dp + 1][rr]);
        int r = r0 + rr;
        int nt = r >> 6;
        int n = (r & 63) + isV * 64;
        size_t base = ((size_t)(e * 4 + nt) * 128 + n) * 1024 + d0 + dp;
        *(uint32_t*)(g_w1 + base) = *(const uint32_t*)p2;
    }
}

// -------- prep: pack Wo[e][r][d] -> g_wop[e][d][k=r] (fp16) --------
__global__ void pack_wo_kernel(const float* __restrict__ Wo) {
    int e = blockIdx.z;
    const float* W = Wo + (size_t)e * RR * DD;   // [r][d]

    __shared__ float tile[32][33];               // tile[r][d]
    int d0 = blockIdx.x * 32, r0 = blockIdx.y * 32;
    int tid = threadIdx.x;

    int rl = tid >> 3, dl = (tid & 7) * 4;
    float4 v = *(const float4*)(W + (size_t)(r0 + rl) * DD + d0 + dl);
    tile[rl][dl + 0] = v.x; tile[rl][dl + 1] = v.y;
    tile[rl][dl + 2] = v.z; tile[rl][dl + 3] = v.w;
    __syncthreads();

    int rp = (tid & 15) * 2;
#pragma unroll
    for (int dd = tid >> 4; dd < 32; dd += 16) {
        __half p2[2];
        p2[0] = __float2half_rn(tile[rp][dd]);
        p2[1] = __float2half_rn(tile[rp + 1][dd]);
        size_t base = ((size_t)e * DD + d0 + dd) * 256 + r0 + rp;
        *(uint32_t*)(g_wop + base) = *(const uint32_t*)p2;
    }
}

// ==================== single-term fp16 MMA core ====================
// Stage (32 KB): [A 16K][B 16K]; 3 stages = 96 KB -> 2 CTAs/SM.
// BM=128, BN=128, BK=64. 8 warps as 2(m) x 4(n); warptile 64m x 32n.
// One __syncthreads per mainloop iteration (loads issued 2 stages ahead).
#define BOFF   16384
#define STAGE  32768
#define CPAD   132
#define MMA_DSMEM (3 * STAGE)   // 98304; epilogue 128*132*4 = 67584 fits

struct MmaCore {
    uint32_t rowA[4];
    uint32_t rowB[2];
    int koct, rx;
};
__device__ __forceinline__ void mma_core_init(MmaCore& mc, int wid, int lane) {
    int wm = wid & 1, wn = wid >> 1;
    int rloc = lane & 15;
    mc.koct = lane >> 4;
    mc.rx = rloc & 7;
#pragma unroll
    for (int im = 0; im < 4; im++) mc.rowA[im] = (uint32_t)(wm * 64 + im * 16 + rloc) * 128u;
#pragma unroll
    for (int h = 0; h < 2; h++) mc.rowB[h] = (uint32_t)(wn * 32 + h * 16 + rloc) * 128u;
}
__device__ __forceinline__ void mma_chunk(const MmaCore& mc, uint32_t sb, float c[4][4][4]) {
#pragma unroll
    for (int ks = 0; ks < 4; ks++) {
        uint32_t kx = (uint32_t)(((2 * ks + mc.koct) ^ mc.rx) << 4);
        uint32_t a[4][4];
#pragma unroll
        for (int im = 0; im < 4; im++) ldsm_x4(a[im], sb + mc.rowA[im] + kx);
#pragma unroll
        for (int h = 0; h < 2; h++) {
            uint32_t b[4];
            ldsm_x4(b, sb + BOFF + mc.rowB[h] + kx);
#pragma unroll
            for (int im = 0; im < 4; im++) {
                mma_f16(c[im][2 * h],     a[im], b[0], b[2]);
                mma_f16(c[im][2 * h + 1], a[im], b[1], b[3]);
            }
        }
    }
}

// ==================== pass1: slots x D * W1 -> U|V, fuse SwiGLU ====================
__global__ __launch_bounds__(256, 2)
void pass1_mma() {
    int e = blockIdx.z;
    int nt = blockIdx.y;                 // cols 0..63 = U rows 64nt.., 64..127 = V
    int cnt = g_count[e];
    int mbase = blockIdx.x * 128;
    if (mbase >= cnt) return;

    extern __shared__ char sm[];
    uint32_t smb = smem_u32(sm);
    __shared__ int   s_sidx[128];
    __shared__ int   s_tok[128];
    __shared__ float s_gate[128];

    int tid = threadIdx.x, lane = tid & 31, wid = tid >> 5;

    if (tid < 128) {
        int slot = mbase + tid;
        bool v = slot < cnt;
        int sidx = v ? g_sidx[e * T_TOT + slot] : 0;
        s_sidx[tid] = sidx;
        s_tok[tid]  = v ? (sidx >> 1) : 0;
        s_gate[tid] = v ? g_gate[e * T_TOT + slot] : 0.f;
    }
    __syncthreads();

    // loaders: A and B tiles both 128 rows x 128B; 2 threads per row
    int row = tid >> 1, hf = tid & 1;
    size_t arow = (size_t)s_tok[row] * DD + hf * 32;
    const __half* bsrc = g_w1 + ((size_t)(e * 4 + nt) * 128 + row) * 1024 + hf * 32;
    uint32_t swo[4];
#pragma unroll
    for (int i = 0; i < 4; i++) swo[i] = sw_off(row, hf * 4 + i);

    auto loadStage = [&](int kc, int s) {
        uint32_t dst = smb + s * STAGE;
        const __half* aa = g_x16 + arow + kc * 64;
        const __half* bb = bsrc + kc * 64;
#pragma unroll
        for (int i = 0; i < 4; i++) {
            cp16(dst + swo[i],        aa + i * 8);
            cp16(dst + BOFF + swo[i], bb + i * 8);
        }
    };

    MmaCore mc;
    mma_core_init(mc, wid, lane);
    int wm = wid & 1, wn = wid >> 1;

    float c[4][4][4];
#pragma unroll
    for (int i = 0; i < 4; i++)
#pragma unroll
        for (int j = 0; j < 4; j++)
#pragma unroll
            for (int q = 0; q < 4; q++) c[i][j][q] = 0.f;

    const int NIT = DD / 64;   // 16
    loadStage(0, 0); CP_COMMIT();
    loadStage(1, 1); CP_COMMIT();
    for (int it = 0; it < NIT; ++it) {
        if (it == NIT - 1) { CP_WAIT0(); } else { CP_WAIT1(); }
        __syncthreads();
        if (it + 2 < NIT) { loadStage(it + 2, (it + 2) % 3); CP_COMMIT(); }
        mma_chunk(mc, smb + (it % 3) * STAGE, c);
    }
    __syncthreads();

    // epilogue: stage C (128x128 fp32), fuse s = gate*silu(u)*v, store fp16
    float* smC = (float*)sm;
#pragma unroll
    for (int im = 0; im < 4; im++) {
        int r1 = wm * 64 + im * 16 + (lane >> 2);
#pragma unroll
        for (int jn = 0; jn < 4; jn++) {
            int cb = wn * 32 + jn * 8 + ((lane & 3) << 1);
            *(float2*)&smC[r1 * CPAD + cb]       = make_float2(c[im][jn][0], c[im][jn][1]);
            *(float2*)&smC[(r1 + 8) * CPAD + cb] = make_float2(c[im][jn][2], c[im][jn][3]);
        }
    }
    __syncthreads();

    int rr = tid >> 1, seg = tid & 1;
    int slot = mbase + rr;
    if (slot < cnt) {
        int sidx = s_sidx[rr];
        float gate = s_gate[rr];
        size_t ob = (size_t)sidx * RR + nt * 64 + seg * 32;
        const float* uptr = &smC[rr * CPAD + seg * 32];
        const float* vptr = uptr + 64;
#pragma unroll
        for (int j = 0; j < 32; j += 2) {
            float u0 = uptr[j], u1 = uptr[j + 1];
            float v0 = vptr[j], v1 = vptr[j + 1];
            float s0 = gate * u0 * v0 / (1.f + __expf(-u0));
            float s1 = gate * u1 * v1 / (1.f + __expf(-u1));
            __half h2[2];
            h2[0] = __float2half_rn(s0);
            h2[1] = __float2half_rn(s1);
            *(uint32_t*)(g_s16 + ob + j) = *(const uint32_t*)h2;
        }
    }
}

// ==================== pass2: slots x R * Wo -> g_Y ====================
__global__ __launch_bounds__(256, 2)
void pass2_mma() {
    int e = blockIdx.z;
    int ntile = blockIdx.y;              // d-base = ntile*128
    int cnt = g_count[e];
    int mbase = blockIdx.x * 128;
    if (mbase >= cnt) return;

    extern __shared__ char sm[];
    uint32_t smb = smem_u32(sm);
    __shared__ int s_row[128];
    __shared__ int s_val[128];

    int tid = threadIdx.x, lane = tid & 31, wid = tid >> 5;

    if (tid < 128) {
        int slot = mbase + tid;
        bool v = slot < cnt;
        s_row[tid] = v ? g_sidx[e * T_TOT + slot] : 0;
        s_val[tid] = v ? 1 : 0;
    }
    __syncthreads();

    int row = tid >> 1, hf = tid & 1;
    size_t arow = (size_t)s_row[row] * RR + hf * 32;
    const __half* bsrc = g_wop + ((size_t)e * DD + ntile * 128 + row) * 256 + hf * 32;
    uint32_t swo[4];
#pragma unroll
    for (int i = 0; i < 4; i++) swo[i] = sw_off(row, hf * 4 + i);

    auto loadStage = [&](int kc, int s) {
        uint32_t dst = smb + s * STAGE;
        const __half* aa = g_s16 + arow + kc * 64;
        const __half* bb = bsrc + kc * 64;
#pragma unroll
        for (int i = 0; i < 4; i++) {
            cp16(dst + swo[i],        aa + i * 8);
            cp16(dst + BOFF + swo[i], bb + i * 8);
        }
    };

    MmaCore mc;
    mma_core_init(mc, wid, lane);
    int wm = wid & 1, wn = wid >> 1;

    float c[4][4][4];
#pragma unroll
    for (int i = 0; i < 4; i++)
#pragma unroll
        for (int j = 0; j < 4; j++)
#pragma unroll
            for (int q = 0; q < 4; q++) c[i][j][q] = 0.f;

    const int NIT = RR / 64;   // 4
    loadStage(0, 0); CP_COMMIT();
    loadStage(1, 1); CP_COMMIT();
    for (int it = 0; it < NIT; ++it) {
        if (it == NIT - 1) { CP_WAIT0(); } else { CP_WAIT1(); }
        __syncthreads();
        if (it + 2 < NIT) { loadStage(it + 2, (it + 2) % 3); CP_COMMIT(); }
        mma_chunk(mc, smb + (it % 3) * STAGE, c);
    }

    // epilogue: plain float2 stores into per-slot Y rows
#pragma unroll
    for (int im = 0; im < 4; im++) {
        int rl = wm * 64 + im * 16 + (lane >> 2);
        int ok0 = s_val[rl], ok1 = s_val[rl + 8];
        int r0 = s_row[rl],  r1 = s_row[rl + 8];
#pragma unroll
        for (int jn = 0; jn < 4; jn++) {
            int col = ntile * 128 + wn * 32 + jn * 8 + ((lane & 3) << 1);
            if (ok0) *(float2*)(g_Y + (size_t)r0 * DD + col) = make_float2(c[im][jn][0], c[im][jn][1]);
            if (ok1) *(float2*)(g_Y + (size_t)r1 * DD + col) = make_float2(c[im][jn][2], c[im][jn][3]);
        }
    }
}

// -------- combine: out[t] = Y[2t] + Y[2t+1] --------
__global__ void combine_kernel(float4* __restrict__ out4) {
    const int D4 = DD / 4;
    int n = T_TOT * D4;
    int stride = gridDim.x * blockDim.x;
    const float4* Y4 = (const float4*)g_Y;
    for (int i = blockIdx.x * blockDim.x + threadIdx.x; i < n; i += stride) {
        int t = i / D4, d4 = i - t * D4;
        float4 a = Y4[(size_t)(2 * t) * D4 + d4];
        float4 b = Y4[(size_t)(2 * t + 1) * D4 + d4];
        out4[i] = make_float4(a.x + b.x, a.y + b.y, a.z + b.z, a.w + b.w);
    }
}

// -------- launch (pass1_mma at launch slot #4 for ncu capture) --------
extern "C" void kernel_launch(void* const* d_in, const int* in_sizes, int n_in,
                              void* d_out, int out_size) {
    (void)in_sizes; (void)n_in; (void)out_size;
    const float* x  = (const float*)d_in[0];
    const float* gw = (const float*)d_in[1];
    const float* Wu = (const float*)d_in[2];
    const float* Wv = (const float*)d_in[3];
    const float* Wo = (const float*)d_in[4];
    float* out = (float*)d_out;

    cudaFuncSetAttribute(pass1_mma, cudaFuncAttributeMaxDynamicSharedMemorySize, MMA_DSMEM);
    cudaFuncSetAttribute(pass2_mma, cudaFuncAttributeMaxDynamicSharedMemorySize, MMA_DSMEM);

    init_kernel<<<1, 32>>>();                                       // 1
    router_split_kernel<<<T_TOT / 8, 256>>>(x, gw);                 // 2
    pack_w1_kernel<<<dim3(DD / 32, RR / 32, EE * 2), 256>>>(Wu, Wv);// 3

    dim3 g1(64, 4, EE);    // M-tiles x r-tiles(64) x experts (early-exit on count)
    pass1_mma<<<g1, 256, MMA_DSMEM>>>();                            // 4  <- profiled

    pack_wo_kernel<<<dim3(DD / 32, RR / 32, EE), 256>>>(Wo);        // 5

    dim3 g2(64, 8, EE);    // M-tiles x d-tiles(128) x experts
    pass2_mma<<<g2, 256, MMA_DSMEM>>>();                            // 6

    combine_kernel<<<1024, 256>>>((float4*)out);                    // 7
}